// round 11
// baseline (speedup 1.0000x reference)
#include <cuda_runtime.h>
#include <cuda_fp16.h>
#include <cstddef>
#include <cstdint>

#define BB 4
#define NN 4096
#define KK 16
#define DP 64
#define DM 256
#define NPTS (BB*NN)
#define MTOT (NPTS*KK)

// ---------------- device-global scratch (no allocs allowed) ----------------
__device__ float  g_WpostT[DM*DP];   // [j][p] fp32
__device__ __half g_Wpreh[DM*DP];    // [n=256][k=64]
__device__ __half g_WQh [DM*DM];     // [n][k]
__device__ __half g_WKh [DM*DM];
__device__ __half g_WVh [DM*DM];
__device__ __half g_Wprojh[DM*DM];
__device__ __half g_Wp2h[DM*DM];
__device__ __half g_Wa1h[DM*DM];
__device__ __half g_Wa2h[DM*DM];
__device__ float g_Q [NPTS*DM];
__device__ float g_Kf[NPTS*DM];
__device__ float g_Vf[NPTS*DM];
__device__ int   g_idx[NPTS*KK];
__device__ float g_res[(size_t)NPTS*DM];

// ---------------- helpers ----------------
__device__ __forceinline__ uint32_t smem_u32(const void* p) {
    uint32_t a;
    asm("{ .reg .u64 t; cvta.to.shared.u64 t, %1; cvt.u32.u64 %0, t; }" : "=r"(a) : "l"(p));
    return a;
}
#define CP16(dst, src) asm volatile("cp.async.cg.shared.global [%0], [%1], 16;" :: "r"(dst), "l"(src) : "memory")
#define CP_COMMIT()    asm volatile("cp.async.commit_group;" ::: "memory")
#define CP_WAIT1()     asm volatile("cp.async.wait_group 1;" ::: "memory")
#define CP_WAIT0()     asm volatile("cp.async.wait_group 0;" ::: "memory")
#define LDSM4(r0,r1,r2,r3,a) \
    asm volatile("ldmatrix.sync.aligned.m8n8.x4.shared.b16 {%0,%1,%2,%3}, [%4];" \
                 : "=r"(r0),"=r"(r1),"=r"(r2),"=r"(r3) : "r"(a))

__device__ __forceinline__ void mma16816(float* c, const uint32_t* a, uint32_t b0, uint32_t b1) {
    asm volatile("mma.sync.aligned.m16n8k16.row.col.f32.f16.f16.f32 "
        "{%0,%1,%2,%3}, {%4,%5,%6,%7}, {%8,%9}, {%0,%1,%2,%3};"
        : "+f"(c[0]), "+f"(c[1]), "+f"(c[2]), "+f"(c[3])
        : "r"(a[0]), "r"(a[1]), "r"(a[2]), "r"(a[3]), "r"(b0), "r"(b1));
}

#define APITCH_B 528
#define ABYTES64  (64*APITCH_B)           // 33792
#define BBYTES    (256*144)               // 36864 (qkv/final B chunks, k=64)
#define QKV_SMEM  (ABYTES64 + 2*BBYTES)   // 107520

// mega: 64 rows, U in smem, k-chunk = 32 (B pitch 80B, conflict-free)
#define UOFF      ABYTES64
#define BOFF      (2*ABYTES64)            // 67584
#define BPITCH32  80
#define BBYTES32  (256*BPITCH32)          // 20480
#define MEGA_SMEM (2*ABYTES64 + 2*BBYTES32) // 108544

__device__ __forceinline__ void warp_bfly2(float& s, float& s2)
{
    #pragma unroll
    for (int o = 16; o; o >>= 1) {
        s  += __shfl_xor_sync(0xffffffffu, s , o);
        s2 += __shfl_xor_sync(0xffffffffu, s2, o);
    }
}

// ---------------- weight prep ----------------
__global__ void prep_kernel(const float* __restrict__ W_pre,
                            const float* __restrict__ WQ,  const float* __restrict__ WK,
                            const float* __restrict__ WV,  const float* __restrict__ Wproj,
                            const float* __restrict__ W_post,
                            const float* __restrict__ Wp2, const float* __restrict__ Wa1,
                            const float* __restrict__ Wa2)
{
    int t = blockIdx.x * blockDim.x + threadIdx.x;
    if (t < DM*DP) {
        g_Wpreh[t] = __float2half_rn(W_pre[t]);
        int p = t >> 8, j = t & 255;
        g_WpostT[j*DP + p] = W_post[t];
    }
    if (t < DM*DM) {
        g_WQh  [t] = __float2half_rn(WQ[t]);
        g_WKh  [t] = __float2half_rn(WK[t]);
        g_WVh  [t] = __float2half_rn(WV[t]);
        g_Wprojh[t] = __float2half_rn(Wproj[t]);
        g_Wp2h[t] = __float2half_rn(Wp2[t]);
        g_Wa1h[t] = __float2half_rn(Wa1[t]);
        g_Wa2h[t] = __float2half_rn(Wa2[t]);
    }
}

// ---------------- kNN v3 (unchanged) ----------------
__device__ __forceinline__ void ins16(float* bd, int* bi, float d, int m)
{
    #pragma unroll
    for (int i = 15; i >= 1; i--) {
        bool c1 = d < bd[i-1];
        bool c2 = d < bd[i];
        float nb = c1 ? bd[i-1] : (c2 ? d : bd[i]);
        int   ni = c1 ? bi[i-1] : (c2 ? m : bi[i]);
        bd[i] = nb; bi[i] = ni;
    }
    if (d < bd[0]) { bi[0] = m; bd[0] = d; }
}

__global__ void __launch_bounds__(256) knn_kernel(const float* __restrict__ xyz)
{
    extern __shared__ float4 pts[];
    __shared__ float md[64][3][16];
    __shared__ int   mi[64][3][16];

    int b     = blockIdx.x >> 6;
    int chunk = blockIdx.x & 63;
    const float* xb = xyz + (size_t)b * NN * 3;
    for (int m = threadIdx.x; m < NN; m += 256)
        pts[m] = make_float4(xb[m*3], xb[m*3+1], xb[m*3+2], 0.f);
    __syncthreads();

    int qloc = threadIdx.x & 63;
    int sub  = threadIdx.x >> 6;
    int qi   = chunk*64 + qloc;
    float4 qp = pts[qi];

    float bd[16]; int bi[16];
    #pragma unroll
    for (int i = 0; i < 16; i++) { bd[i] = 3.4e38f; bi[i] = 0; }

    int base = sub * 1024;
    #pragma unroll 2
    for (int m = base; m < base + 1024; m += 2) {
        float4 p0 = pts[m], p1 = pts[m+1];
        float dx0 = qp.x-p0.x, dy0 = qp.y-p0.y, dz0 = qp.z-p0.z;
        float dx1 = qp.x-p1.x, dy1 = qp.y-p1.y, dz1 = qp.z-p1.z;
        float d0 = fmaf(dx0,dx0, fmaf(dy0,dy0, dz0*dz0));
        float d1 = fmaf(dx1,dx1, fmaf(dy1,dy1, dz1*dz1));
        if (d0 < bd[15]) ins16(bd, bi, d0, m);
        if (d1 < bd[15]) ins16(bd, bi, d1, m+1);
    }

    if (sub) {
        #pragma unroll
        for (int i = 0; i < 16; i++) { md[qloc][sub-1][i] = bd[i]; mi[qloc][sub-1][i] = bi[i]; }
    }
    __syncthreads();
    if (sub == 0) {
        #pragma unroll
        for (int l = 0; l < 3; l++) {
            #pragma unroll
            for (int i = 0; i < 16; i++) {
                float d = md[qloc][l][i];
                if (d < bd[15]) ins16(bd, bi, d, mi[qloc][l][i]);
            }
        }
        #pragma unroll
        for (int i = 0; i < 16; i++)
            g_idx[(size_t)(b*NN + qi)*KK + i] = bi[i];
    }
}

// ---------------- 512-thread MMA helpers (qkv / final, unchanged) -------------
__device__ __forceinline__ void mma_tile512(uint32_t ab, uint32_t bb, float acc[2][4][4])
{
    #pragma unroll
    for (int ks = 0; ks < 4; ks++) {
        uint32_t af[2][4], bf[2][4];
        LDSM4(af[0][0], af[0][1], af[0][2], af[0][3], ab + ks*32);
        LDSM4(af[1][0], af[1][1], af[1][2], af[1][3], ab + 16*APITCH_B + ks*32);
        LDSM4(bf[0][0], bf[0][1], bf[0][2], bf[0][3], bb + ks*32);
        LDSM4(bf[1][0], bf[1][1], bf[1][2], bf[1][3], bb + 16*144 + ks*32);
        #pragma unroll
        for (int mt = 0; mt < 2; mt++)
            #pragma unroll
            for (int nt = 0; nt < 4; nt++)
                mma16816(acc[mt][nt], af[mt],
                         bf[nt >> 1][(nt & 1)*2], bf[nt >> 1][(nt & 1)*2 + 1]);
    }
}

__device__ __forceinline__ void load_w512(uint32_t sB, const __half* __restrict__ W,
                                          int kt, int buf, int tid)
{
    uint32_t base = sB + (uint32_t)buf*BBYTES;
    #pragma unroll
    for (int i = 0; i < 4; i++) {
        int ch = tid + i*512;
        int r = ch >> 3, c = ch & 7;
        CP16(base + r*144 + c*16, W + (size_t)r*256 + kt*64 + c*8);
    }
}

__device__ __forceinline__ void zero_acc2(float acc[2][4][4])
{
    #pragma unroll
    for (int mt = 0; mt < 2; mt++)
        #pragma unroll
        for (int nt = 0; nt < 4; nt++)
            #pragma unroll
            for (int j = 0; j < 4; j++) acc[mt][nt][j] = 0.f;
}

// ---------------- LN epilogue helpers ----------------
__device__ __forceinline__ void ln_reduce(float acc[2][4][4], float2 (*red)[8],
                                          int lane, int wn, int wm2)
{
    #pragma unroll
    for (int mt = 0; mt < 2; mt++) {
        int gmt = wm2*2 + mt;
        int r0 = gmt*16 + (lane >> 2), r1 = r0 + 8;
        float s0=0.f, q0=0.f, s1=0.f, q1=0.f;
        #pragma unroll
        for (int nt = 0; nt < 4; nt++) {
            float a0=acc[mt][nt][0], a1=acc[mt][nt][1];
            float a2=acc[mt][nt][2], a3=acc[mt][nt][3];
            s0 += a0+a1; q0 += a0*a0+a1*a1;
            s1 += a2+a3; q1 += a2*a2+a3*a3;
        }
        #pragma unroll
        for (int o = 1; o < 4; o <<= 1) {
            s0 += __shfl_xor_sync(~0u, s0, o); q0 += __shfl_xor_sync(~0u, q0, o);
            s1 += __shfl_xor_sync(~0u, s1, o); q1 += __shfl_xor_sync(~0u, q1, o);
        }
        if ((lane & 3) == 0) {
            red[r0][wn] = make_float2(s0, q0);
            red[r1][wn] = make_float2(s1, q1);
        }
    }
    __syncthreads();
}

__device__ __forceinline__ void ln_stats(float2 (*red)[8], int row, float& mu, float& rs)
{
    float S = 0.f, Q = 0.f;
    #pragma unroll
    for (int i = 0; i < 8; i++) { float2 e = red[row][i]; S += e.x; Q += e.y; }
    mu = S * (1.f/DM);
    float var = Q * (1.f/DM) - mu*mu;
    rs = rsqrtf(var + 1e-5f);
}

// ---------------- qkv via HMMA (unchanged) ----------------
__global__ void __launch_bounds__(512) qkvmma_kernel(
    const float* __restrict__ features, const float* __restrict__ b_pre,
    const float* __restrict__ gdm, const float* __restrict__ bdm)
{
    extern __shared__ char smemc[];
    __shared__ float2 red[64][8];
    uint32_t sA = smem_u32(smemc);
    uint32_t sB = sA + ABYTES64;
    const int tid = threadIdx.x, lane = tid & 31, w = tid >> 5;
    const int wn = w & 7, wm2 = w >> 3;
    const int p0 = blockIdx.x * 64;

    {
        #pragma unroll
        for (int i = 0; i < 4; i++) {
            int ch = tid + i*512; int r = ch >> 3, c = ch & 7;
            CP16(sB + r*144 + c*16, g_Wpreh + r*64 + c*8);
        }
        CP_COMMIT();
        load_w512(sB, g_WQh, 0, 1, tid); CP_COMMIT();
    }

    for (int ch = tid; ch < 64*32; ch += 512) {
        int r = ch >> 5, c2 = ch & 31;
        float2 v = *(const float2*)&features[(size_t)(p0 + r)*DP + c2*2];
        *(half2*)(smemc + (size_t)r*APITCH_B + c2*4) = __floats2half2_rn(v.x, v.y);
    }

    const uint32_t aAddr = sA + (uint32_t)(wm2*32 + (lane & 15))*APITCH_B + (lane >> 4)*16;
    const uint32_t bAddr = sB + (uint32_t)(wn*32 + ((lane >> 4) & 1)*8 + (lane & 7))*144
                              + ((lane >> 3) & 1)*16;

    float acc[2][4][4];

    zero_acc2(acc);
    CP_WAIT1(); __syncthreads();
    mma_tile512(aAddr, bAddr, acc);
    __syncthreads();
    load_w512(sB, g_WQh, 1, 0, tid); CP_COMMIT();
    {
        #pragma unroll
        for (int mt = 0; mt < 2; mt++) {
            int gmt = wm2*2 + mt;
            int r0 = gmt*16 + (lane >> 2), r1 = r0 + 8;
            #pragma unroll
            for (int nt = 0; nt < 4; nt++) {
                int col = wn*32 + nt*8 + (lane & 3)*2;
                float b0 = b_pre[col], b1 = b_pre[col+1];
                *(half2*)(smemc + (size_t)r0*APITCH_B + col*2) =
                    __floats2half2_rn(acc[mt][nt][0] + b0, acc[mt][nt][1] + b1);
                *(half2*)(smemc + (size_t)r1*APITCH_B + col*2) =
                    __floats2half2_rn(acc[mt][nt][2] + b0, acc[mt][nt][3] + b1);
            }
        }
    }

    const __half* Ws[3] = { g_WQh, g_WKh, g_WVh };
    float* outs[3] = { g_Q, g_Kf, g_Vf };
    for (int s = 0; s < 3; s++) {
        zero_acc2(acc);
        for (int kt = 0; kt < 4; kt++) {
            int c = 1 + s*4 + kt;
            if (c == 12) { CP_WAIT0(); } else { CP_WAIT1(); }
            __syncthreads();
            mma_tile512(aAddr + kt*128, bAddr + (uint32_t)(c & 1)*BBYTES, acc);
            __syncthreads();
            int nc = c + 2;
            if (nc <= 12) {
                int ns = (nc - 1) >> 2, nkt = (nc - 1) & 3;
                load_w512(sB, Ws[ns], nkt, nc & 1, tid);
                CP_COMMIT();
            }
        }
        ln_reduce(acc, red, lane, wn, wm2);
        float* outg = outs[s];
        #pragma unroll
        for (int mt = 0; mt < 2; mt++) {
            int gmt = wm2*2 + mt;
            int r0 = gmt*16 + (lane >> 2), r1 = r0 + 8;
            float mu0, rs0, mu1, rs1;
            ln_stats(red, r0, mu0, rs0);
            ln_stats(red, r1, mu1, rs1);
            #pragma unroll
            for (int nt = 0; nt < 4; nt++) {
                int col = wn*32 + nt*8 + (lane & 3)*2;
                float g0 = gdm[col], g1 = gdm[col+1];
                float b0 = bdm[col], b1 = bdm[col+1];
                *(float2*)&outg[(size_t)(p0+r0)*DM + col] = make_float2(
                    (acc[mt][nt][0]-mu0)*rs0*g0 + b0, (acc[mt][nt][1]-mu0)*rs0*g1 + b1);
                *(float2*)&outg[(size_t)(p0+r1)*DM + col] = make_float2(
                    (acc[mt][nt][2]-mu1)*rs1*g0 + b0, (acc[mt][nt][3]-mu1)*rs1*g1 + b1);
            }
        }
        __syncthreads();
    }
}

// ---------------- mega kernel: 256 thr, 64 rows, k-chunk 32, 2 CTAs/SM --------
__device__ __forceinline__ void load_w32(uint32_t sB, const __half* __restrict__ W,
                                         int kt, int buf, int tid)
{
    // chunk = 256 weight rows x 32 k (64 B/row), pitch 80 B
    uint32_t base = sB + (uint32_t)buf*BBYTES32;
    #pragma unroll
    for (int i = 0; i < 4; i++) {
        int ch = tid + i*256;
        int r = ch >> 2, c = ch & 3;
        CP16(base + r*BPITCH32 + c*16, W + (size_t)r*256 + kt*32 + c*8);
    }
}

__global__ void __launch_bounds__(256, 2) mega_kernel(
    const float* __restrict__ xyz, const float* __restrict__ Wp1)
{
    extern __shared__ char smemc[];
    uint32_t sA = smem_u32(smemc);
    uint32_t sB = sA + BOFF;

    const int tid  = threadIdx.x;
    const int lane = tid & 31, wn = tid >> 5;    // 8 warps, each owns 32 cols
    const int m0    = blockIdx.x * 64;
    const int pbase = m0 >> 4;                   // 4 points per CTA
    const int bq    = pbase >> 12;

    __shared__ float rel3[64][3];
    __shared__ int   idxs[64];

    const __half* Ws[3] = { g_Wp2h, g_Wa1h, g_Wa2h };

    load_w32(sB, g_Wp2h, 0, 0, tid); CP_COMMIT();
    load_w32(sB, g_Wp2h, 1, 1, tid); CP_COMMIT();

    if (tid < 64) {
        int m  = m0 + tid;
        int pt = m >> 4;
        int n  = pt & (NN - 1);
        int id = g_idx[(size_t)pt*KK + (m & 15)];
        idxs[tid] = id;
        const float* xb = xyz + (size_t)bq*NN*3;
        rel3[tid][0] = xb[n*3 + 0] - xb[id*3 + 0];
        rel3[tid][1] = xb[n*3 + 1] - xb[id*3 + 1];
        rel3[tid][2] = xb[n*3 + 2] - xb[id*3 + 2];
    }
    __syncthreads();

    {
        int c0 = (tid & 127)*2;
        int j0 = (tid >> 7)*32;
        float a0 = Wp1[c0*3+0], a1 = Wp1[c0*3+1], a2 = Wp1[c0*3+2];
        float d0 = Wp1[c0*3+3], d1 = Wp1[c0*3+4], d2 = Wp1[c0*3+5];
        #pragma unroll 8
        for (int j = j0; j < j0 + 32; j++) {
            float h0 = fmaf(a0, rel3[j][0], fmaf(a1, rel3[j][1], a2*rel3[j][2]));
            float h1 = fmaf(d0, rel3[j][0], fmaf(d1, rel3[j][1], d2*rel3[j][2]));
            *(half2*)(smemc + (size_t)j*APITCH_B + c0*2) =
                __floats2half2_rn(fmaxf(h0, 0.f), fmaxf(h1, 0.f));
        }
    }

    const uint32_t aBase = sA + (uint32_t)(lane & 15)*APITCH_B + (lane >> 4)*16;
    const uint32_t bAddr = sB + (uint32_t)(wn*32 + ((lane >> 4) & 1)*8 + (lane & 7))*BPITCH32
                              + ((lane >> 3) & 1)*16;

    float acc[4][4][4];

    #pragma unroll 1
    for (int c = 0; c < 24; c++) {
        const int kt = c & 7;                   // chunk within stage (k-chunk 32)
        if (kt == 0) {
            #pragma unroll
            for (int mt = 0; mt < 4; mt++)
                #pragma unroll
                for (int nt = 0; nt < 4; nt++)
                    #pragma unroll
                    for (int j = 0; j < 4; j++) acc[mt][nt][j] = 0.f;
        }

        if (c >= 22) { CP_WAIT0(); } else { CP_WAIT1(); }
        __syncthreads();

        // MMA on chunk c (buffer c&1): 2 k16 steps
        {
            uint32_t ab = aBase + kt*64;
            uint32_t bb = bAddr + (uint32_t)(c & 1)*BBYTES32;
            #pragma unroll
            for (int ks = 0; ks < 2; ks++) {
                uint32_t bf[2][4];
                LDSM4(bf[0][0], bf[0][1], bf[0][2], bf[0][3], bb + ks*32);
                LDSM4(bf[1][0], bf[1][1], bf[1][2], bf[1][3], bb + 16*BPITCH32 + ks*32);
                #pragma unroll
                for (int mt = 0; mt < 4; mt++) {
                    uint32_t af[4];
                    LDSM4(af[0], af[1], af[2], af[3], ab + mt*(16*APITCH_B) + ks*32);
                    #pragma unroll
                    for (int nt = 0; nt < 4; nt++)
                        mma16816(acc[mt][nt], af,
                                 bf[nt >> 1][(nt & 1)*2], bf[nt >> 1][(nt & 1)*2 + 1]);
                }
            }
        }
        __syncthreads();

        if (c + 2 < 24) {
            int nc = c + 2;
            load_w32(sB, Ws[nc >> 3], nc & 7, c & 1, tid);
            CP_COMMIT();
        }

        if (kt == 7) {
            const int stage = c >> 3;
            const int r0b  = lane >> 2;
            const int colb = wn*32 + (lane & 3)*2;

            if (stage == 0) {
                #pragma unroll
                for (int mt = 0; mt < 4; mt++) {
                    int pt = pbase + mt;
                    int r0 = mt*16 + r0b, r1 = r0 + 8;
                    const float* qp  = g_Q  + (size_t)pt*DM;
                    const float* k0p = g_Kf + ((size_t)(bq << 12) + idxs[r0])*DM;
                    const float* k1p = g_Kf + ((size_t)(bq << 12) + idxs[r1])*DM;
                    const float* v0p = g_Vf + ((size_t)(bq << 12) + idxs[r0])*DM;
                    const float* v1p = g_Vf + ((size_t)(bq << 12) + idxs[r1])*DM;
                    #pragma unroll
                    for (int nt = 0; nt < 4; nt++) {
                        int col = colb + nt*8;
                        float2 q  = *(const float2*)(qp  + col);
                        float2 ka = *(const float2*)(k0p + col);
                        float2 kb = *(const float2*)(k1p + col);
                        float2 va = *(const float2*)(v0p + col);
                        float2 vb = *(const float2*)(v1p + col);
                        float p00 = acc[mt][nt][0], p01 = acc[mt][nt][1];
                        float p10 = acc[mt][nt][2], p11 = acc[mt][nt][3];
                        *(half2*)(smemc + (size_t)r0*APITCH_B + col*2) =
                            __floats2half2_rn(q.x - ka.x + p00, q.y - ka.y + p01);
                        *(half2*)(smemc + (size_t)r1*APITCH_B + col*2) =
                            __floats2half2_rn(q.x - kb.x + p10, q.y - kb.y + p11);
                        *(half2*)(smemc + UOFF + (size_t)r0*APITCH_B + col*2) =
                            __floats2half2_rn(va.x + p00, va.y + p01);
                        *(half2*)(smemc + UOFF + (size_t)r1*APITCH_B + col*2) =
                            __floats2half2_rn(vb.x + p10, vb.y + p11);
                    }
                }
            } else if (stage == 1) {
                #pragma unroll
                for (int mt = 0; mt < 4; mt++) {
                    int r0 = mt*16 + r0b, r1 = r0 + 8;
                    #pragma unroll
                    for (int nt = 0; nt < 4; nt++) {
                        int col = colb + nt*8;
                        *(half2*)(smemc + (size_t)r0*APITCH_B + col*2) =
                            __floats2half2_rn(fmaxf(acc[mt][nt][0], 0.f), fmaxf(acc[mt][nt][1], 0.f));
                        *(half2*)(smemc + (size_t)r1*APITCH_B + col*2) =
                            __floats2half2_rn(fmaxf(acc[mt][nt][2], 0.f), fmaxf(acc[mt][nt][3], 0.f));
                    }
                }
            } else {
                const float sc = 0.0625f;
                #pragma unroll
                for (int mt = 0; mt < 4; mt++) {
                    int pt = pbase + mt;
                    int r0 = mt*16 + r0b, r1 = r0 + 8;
                    #pragma unroll
                    for (int nt = 0; nt < 4; nt++) {
                        int col = colb + nt*8;
                        float2 ua = __half22float2(
                            *(half2*)(smemc + UOFF + (size_t)r0*APITCH_B + col*2));
                        float2 ub = __half22float2(
                            *(half2*)(smemc + UOFF + (size_t)r1*APITCH_B + col*2));
                        float rout[2];
                        #pragma unroll
                        for (int p = 0; p < 2; p++) {
                            float x0 = acc[mt][nt][p]     * sc;
                            float x1 = acc[mt][nt][2 + p] * sc;
                            float mx = fmaxf(x0, x1);
                            #pragma unroll
                            for (int o = 4; o < 32; o <<= 1)
                                mx = fmaxf(mx, __shfl_xor_sync(0xffffffffu, mx, o));
                            float e0 = __expf(x0 - mx), e1 = __expf(x1 - mx);
                            float s  = e0 + e1;
                            float uu0 = p ? ua.y : ua.x;
                            float uu1 = p ? ub.y : ub.x;
                            float ww = e0*uu0 + e1*uu1;
                            #pragma unroll
                            for (int o = 4; o < 32; o <<= 1) {
                                s  += __shfl_xor_sync(0xffffffffu, s , o);
                                ww += __shfl_xor_sync(0xffffffffu, ww, o);
                            }
                            rout[p] = ww / s;
                        }
                        if (lane < 4)
                            *(float2*)&g_res[(size_t)pt*DM + col] = make_float2(rout[0], rout[1]);
                    }
                }
            }
        }
    }
}

// ---------------- final via HMMA (unchanged) ----------------
__global__ void __launch_bounds__(512) finalmma_kernel(
    const float* __restrict__ features, const float* __restrict__ b_post,
    const float* __restrict__ gdm, const float* __restrict__ bdm,
    const float* __restrict__ gdp, const float* __restrict__ bdp,
    float* __restrict__ out)
{
    extern __shared__ char smemc[];
    __shared__ float2 red[64][8];
    uint32_t sA = smem_u32(smemc);
    uint32_t sB = sA + ABYTES64;
    const int tid = threadIdx.x, lane = tid & 31, w = tid >> 5;
    const int wn = w & 7, wm2 = w >> 3;
    const int p0 = blockIdx.x * 64;

    load_w512(sB, g_Wprojh, 0, 0, tid); CP_COMMIT();
    load_w512(sB, g_Wprojh, 1, 1, tid); CP_COMMIT();

    for (int ch = tid; ch < 64*128; ch += 512) {
        int r = ch >> 7, c2 = ch & 127;
        float2 v = *(const float2*)&g_res[(size_t)(p0 + r)*DM + c2*2];
        *(half2*)(smemc + (size_t)r*APITCH_B + c2*4) = __floats2half2_rn(v.x, v.y);
    }

    const uint32_t aAddr = sA + (uint32_t)(wm2*32 + (lane & 15))*APITCH_B + (lane >> 4)*16;
    const uint32_t bAddr = sB + (uint32_t)(wn*32 + ((lane >> 4) & 1)*8 + (lane & 7))*144
                              + ((lane >> 3) & 1)*16;

    float acc[2][4][4];
    zero_acc2(acc);
    for (int kt = 0; kt < 4; kt++) {
        if (kt == 3) { CP_WAIT0(); } else { CP_WAIT1(); }
        __syncthreads();
        mma_tile512(aAddr + kt*128, bAddr + (uint32_t)(kt & 1)*BBYTES, acc);
        __syncthreads();
        if (kt + 2 < 4) { load_w512(sB, g_Wprojh, kt + 2, kt & 1, tid); CP_COMMIT(); }
    }

    ln_reduce(acc, red, lane, wn, wm2);
    #pragma unroll
    for (int mt = 0; mt < 2; mt++) {
        int gmt = wm2*2 + mt;
        int r0 = gmt*16 + (lane >> 2), r1 = r0 + 8;
        float mu0, rs0, mu1, rs1;
        ln_stats(red, r0, mu0, rs0);
        ln_stats(red, r1, mu1, rs1);
        #pragma unroll
        for (int nt = 0; nt < 4; nt++) {
            int col = wn*32 + nt*8 + (lane & 3)*2;
            float g0 = gdm[col], g1 = gdm[col+1];
            float b0 = bdm[col], b1 = bdm[col+1];
            *(half2*)(smemc + (size_t)r0*APITCH_B + col*2) = __floats2half2_rn(
                (acc[mt][nt][0]-mu0)*rs0*g0 + b0, (acc[mt][nt][1]-mu0)*rs0*g1 + b1);
            *(half2*)(smemc + (size_t)r1*APITCH_B + col*2) = __floats2half2_rn(
                (acc[mt][nt][2]-mu1)*rs1*g0 + b0, (acc[mt][nt][3]-mu1)*rs1*g1 + b1);
        }
    }
    __syncthreads();

    const int po = tid & 63, rg = tid >> 6;
    float o[8];
    #pragma unroll
    for (int i = 0; i < 8; i++) o[i] = b_post[po];
    for (int j2 = 0; j2 < 128; j2++) {
        float w0 = g_WpostT[(2*j2)*DP + po];
        float w1 = g_WpostT[(2*j2+1)*DP + po];
        #pragma unroll
        for (int i = 0; i < 8; i++) {
            int r = rg*8 + i;
            half2 zz = *(const half2*)(smemc + (size_t)r*APITCH_B + j2*4);
            float2 zf = __half22float2(zz);
            o[i] = fmaf(w0, zf.x, fmaf(w1, zf.y, o[i]));
        }
    }

    float* obuf = (float*)(smemc + ABYTES64);
    #pragma unroll
    for (int i = 0; i < 8; i++) obuf[(rg*8 + i)*68 + po] = o[i];
    __syncthreads();

    #pragma unroll
    for (int i = 0; i < 4; i++) {
        int row = w*4 + i;
        float x0 = obuf[row*68 + lane], x1 = obuf[row*68 + 32 + lane];
        float s = x0 + x1, s2 = x0*x0 + x1*x1;
        warp_bfly2(s, s2);
        float mu = s*(1.f/DP), var = s2*(1.f/DP) - mu*mu;
        float rs = rsqrtf(var + 1e-5f);
        size_t base = (size_t)(p0 + row)*DP;
        out[base + lane]      = (x0-mu)*rs*gdp[lane]      + bdp[lane]      + features[base + lane];
        out[base + 32 + lane] = (x1-mu)*rs*gdp[32 + lane] + bdp[32 + lane] + features[base + 32 + lane];
    }
}

// ---------------- launch ----------------
extern "C" void kernel_launch(void* const* d_in, const int* in_sizes, int n_in,
                              void* d_out, int out_size)
{
    const float* xyz      = (const float*)d_in[0];
    const float* features = (const float*)d_in[1];
    const float* W_pre    = (const float*)d_in[2];
    const float* b_pre    = (const float*)d_in[3];
    const float* W_post   = (const float*)d_in[4];
    const float* b_post   = (const float*)d_in[5];
    const float* Wp1      = (const float*)d_in[6];
    const float* Wp2      = (const float*)d_in[7];
    const float* Wa1      = (const float*)d_in[8];
    const float* Wa2      = (const float*)d_in[9];
    const float* WQ       = (const float*)d_in[10];
    const float* WK       = (const float*)d_in[11];
    const float* WV       = (const float*)d_in[12];
    const float* Wproj    = (const float*)d_in[13];
    const float* g_dm     = (const float*)d_in[14];
    const float* b_dm     = (const float*)d_in[15];
    const float* g_dp     = (const float*)d_in[16];
    const float* b_dp     = (const float*)d_in[17];
    float* out = (float*)d_out;

    cudaFuncSetAttribute(knn_kernel, cudaFuncAttributeMaxDynamicSharedMemorySize,
                         NN * (int)sizeof(float4));
    cudaFuncSetAttribute(mega_kernel,     cudaFuncAttributeMaxDynamicSharedMemorySize, MEGA_SMEM);
    cudaFuncSetAttribute(qkvmma_kernel,   cudaFuncAttributeMaxDynamicSharedMemorySize, QKV_SMEM);
    cudaFuncSetAttribute(finalmma_kernel, cudaFuncAttributeMaxDynamicSharedMemorySize, QKV_SMEM);

    prep_kernel<<<256, 256>>>(W_pre, WQ, WK, WV, Wproj, W_post, Wp2, Wa1, Wa2);
    knn_kernel<<<BB*64, 256, NN*sizeof(float4)>>>(xyz);
    qkvmma_kernel<<<NPTS/64, 512, QKV_SMEM>>>(features, b_pre, g_dm, b_dm);

    mega_kernel<<<MTOT/64, 256, MEGA_SMEM>>>(xyz, Wp1);

    finalmma_kernel<<<NPTS/64, 512, QKV_SMEM>>>(features, b_post, g_dm, b_dm,
                                                g_dp, b_dp, out);
}

// round 12
// speedup vs baseline: 1.6141x; 1.6141x over previous
#include <cuda_runtime.h>
#include <cuda_fp16.h>
#include <cstddef>
#include <cstdint>

#define BB 4
#define NN 4096
#define KK 16
#define DP 64
#define DM 256
#define NPTS (BB*NN)
#define MTOT (NPTS*KK)

// ---------------- device-global scratch (no allocs allowed) ----------------
__device__ float  g_WpostT[DM*DP];   // [j][p] fp32
__device__ __half g_Wpreh[DM*DP];    // [n=256][k=64]
__device__ __half g_WQh [DM*DM];     // [n][k]
__device__ __half g_WKh [DM*DM];
__device__ __half g_WVh [DM*DM];
__device__ __half g_Wprojh[DM*DM];
__device__ __half g_Wp2h[DM*DM];
__device__ __half g_Wa1h[DM*DM];
__device__ __half g_Wa2h[DM*DM];
__device__ float g_Q [NPTS*DM];
__device__ float g_Kf[NPTS*DM];
__device__ float g_Vf[NPTS*DM];
__device__ int   g_idx[NPTS*KK];
__device__ float g_res[(size_t)NPTS*DM];

// ---------------- helpers ----------------
__device__ __forceinline__ uint32_t smem_u32(const void* p) {
    uint32_t a;
    asm("{ .reg .u64 t; cvta.to.shared.u64 t, %1; cvt.u32.u64 %0, t; }" : "=r"(a) : "l"(p));
    return a;
}
#define CP16(dst, src) asm volatile("cp.async.cg.shared.global [%0], [%1], 16;" :: "r"(dst), "l"(src) : "memory")
#define CP_COMMIT()    asm volatile("cp.async.commit_group;" ::: "memory")
#define CP_WAIT1()     asm volatile("cp.async.wait_group 1;" ::: "memory")
#define CP_WAIT0()     asm volatile("cp.async.wait_group 0;" ::: "memory")
#define LDSM4(r0,r1,r2,r3,a) \
    asm volatile("ldmatrix.sync.aligned.m8n8.x4.shared.b16 {%0,%1,%2,%3}, [%4];" \
                 : "=r"(r0),"=r"(r1),"=r"(r2),"=r"(r3) : "r"(a))

__device__ __forceinline__ void mma16816(float* c, const uint32_t* a, uint32_t b0, uint32_t b1) {
    asm volatile("mma.sync.aligned.m16n8k16.row.col.f32.f16.f16.f32 "
        "{%0,%1,%2,%3}, {%4,%5,%6,%7}, {%8,%9}, {%0,%1,%2,%3};"
        : "+f"(c[0]), "+f"(c[1]), "+f"(c[2]), "+f"(c[3])
        : "r"(a[0]), "r"(a[1]), "r"(a[2]), "r"(a[3]), "r"(b0), "r"(b1));
}

#define APITCH_B 528
#define ABYTES64  (64*APITCH_B)            // 33792
#define ABYTES128 (128*APITCH_B)           // 67584
#define BBYTES    (256*144)                // 36864
#define FIN_SMEM  (ABYTES64  + 2*BBYTES)   // 107520 (finalmma)
#define QKV_SMEM  (ABYTES128 + 2*BBYTES)   // 141312 (qkvmma v2, 128 rows)
#define UOFF      ABYTES128
#define BOFF      (2*ABYTES128)
#define MEGA_SMEM (2*ABYTES128 + 2*BBYTES) // 208896 (mega, R10 config)

__device__ __forceinline__ void warp_bfly2(float& s, float& s2)
{
    #pragma unroll
    for (int o = 16; o; o >>= 1) {
        s  += __shfl_xor_sync(0xffffffffu, s , o);
        s2 += __shfl_xor_sync(0xffffffffu, s2, o);
    }
}

// ---------------- weight prep ----------------
__global__ void prep_kernel(const float* __restrict__ W_pre,
                            const float* __restrict__ WQ,  const float* __restrict__ WK,
                            const float* __restrict__ WV,  const float* __restrict__ Wproj,
                            const float* __restrict__ W_post,
                            const float* __restrict__ Wp2, const float* __restrict__ Wa1,
                            const float* __restrict__ Wa2)
{
    int t = blockIdx.x * blockDim.x + threadIdx.x;
    if (t < DM*DP) {
        g_Wpreh[t] = __float2half_rn(W_pre[t]);
        int p = t >> 8, j = t & 255;
        g_WpostT[j*DP + p] = W_post[t];
    }
    if (t < DM*DM) {
        g_WQh  [t] = __float2half_rn(WQ[t]);
        g_WKh  [t] = __float2half_rn(WK[t]);
        g_WVh  [t] = __float2half_rn(WV[t]);
        g_Wprojh[t] = __float2half_rn(Wproj[t]);
        g_Wp2h[t] = __float2half_rn(Wp2[t]);
        g_Wa1h[t] = __float2half_rn(Wa1[t]);
        g_Wa2h[t] = __float2half_rn(Wa2[t]);
    }
}

// ---------------- kNN v3 (unchanged) ----------------
__device__ __forceinline__ void ins16(float* bd, int* bi, float d, int m)
{
    #pragma unroll
    for (int i = 15; i >= 1; i--) {
        bool c1 = d < bd[i-1];
        bool c2 = d < bd[i];
        float nb = c1 ? bd[i-1] : (c2 ? d : bd[i]);
        int   ni = c1 ? bi[i-1] : (c2 ? m : bi[i]);
        bd[i] = nb; bi[i] = ni;
    }
    if (d < bd[0]) { bi[0] = m; bd[0] = d; }
}

__global__ void __launch_bounds__(256) knn_kernel(const float* __restrict__ xyz)
{
    extern __shared__ float4 pts[];
    __shared__ float md[64][3][16];
    __shared__ int   mi[64][3][16];

    int b     = blockIdx.x >> 6;
    int chunk = blockIdx.x & 63;
    const float* xb = xyz + (size_t)b * NN * 3;
    for (int m = threadIdx.x; m < NN; m += 256)
        pts[m] = make_float4(xb[m*3], xb[m*3+1], xb[m*3+2], 0.f);
    __syncthreads();

    int qloc = threadIdx.x & 63;
    int sub  = threadIdx.x >> 6;
    int qi   = chunk*64 + qloc;
    float4 qp = pts[qi];

    float bd[16]; int bi[16];
    #pragma unroll
    for (int i = 0; i < 16; i++) { bd[i] = 3.4e38f; bi[i] = 0; }

    int base = sub * 1024;
    #pragma unroll 2
    for (int m = base; m < base + 1024; m += 2) {
        float4 p0 = pts[m], p1 = pts[m+1];
        float dx0 = qp.x-p0.x, dy0 = qp.y-p0.y, dz0 = qp.z-p0.z;
        float dx1 = qp.x-p1.x, dy1 = qp.y-p1.y, dz1 = qp.z-p1.z;
        float d0 = fmaf(dx0,dx0, fmaf(dy0,dy0, dz0*dz0));
        float d1 = fmaf(dx1,dx1, fmaf(dy1,dy1, dz1*dz1));
        if (d0 < bd[15]) ins16(bd, bi, d0, m);
        if (d1 < bd[15]) ins16(bd, bi, d1, m+1);
    }

    if (sub) {
        #pragma unroll
        for (int i = 0; i < 16; i++) { md[qloc][sub-1][i] = bd[i]; mi[qloc][sub-1][i] = bi[i]; }
    }
    __syncthreads();
    if (sub == 0) {
        #pragma unroll
        for (int l = 0; l < 3; l++) {
            #pragma unroll
            for (int i = 0; i < 16; i++) {
                float d = md[qloc][l][i];
                if (d < bd[15]) ins16(bd, bi, d, mi[qloc][l][i]);
            }
        }
        #pragma unroll
        for (int i = 0; i < 16; i++)
            g_idx[(size_t)(b*NN + qi)*KK + i] = bi[i];
    }
}

// ---------------- shared MMA helpers ----------------
__device__ __forceinline__ void load_w512(uint32_t sB, const __half* __restrict__ W,
                                          int kt, int buf, int tid)
{
    uint32_t base = sB + (uint32_t)buf*BBYTES;
    #pragma unroll
    for (int i = 0; i < 4; i++) {
        int ch = tid + i*512;
        int r = ch >> 3, c = ch & 7;
        CP16(base + r*144 + c*16, W + (size_t)r*256 + kt*64 + c*8);
    }
}

__device__ __forceinline__ void mma_tile512(uint32_t ab, uint32_t bb, float acc[2][4][4])
{
    #pragma unroll
    for (int ks = 0; ks < 4; ks++) {
        uint32_t af[2][4], bf[2][4];
        LDSM4(af[0][0], af[0][1], af[0][2], af[0][3], ab + ks*32);
        LDSM4(af[1][0], af[1][1], af[1][2], af[1][3], ab + 16*APITCH_B + ks*32);
        LDSM4(bf[0][0], bf[0][1], bf[0][2], bf[0][3], bb + ks*32);
        LDSM4(bf[1][0], bf[1][1], bf[1][2], bf[1][3], bb + 16*144 + ks*32);
        #pragma unroll
        for (int mt = 0; mt < 2; mt++)
            #pragma unroll
            for (int nt = 0; nt < 4; nt++)
                mma16816(acc[mt][nt], af[mt],
                         bf[nt >> 1][(nt & 1)*2], bf[nt >> 1][(nt & 1)*2 + 1]);
    }
}

// 128-row tile: 4 m-tiles per warp (rows wm2*64 .. +64)
__device__ __forceinline__ void mma_tile128(uint32_t ab, uint32_t bb, float acc[4][4][4])
{
    #pragma unroll
    for (int ks = 0; ks < 4; ks++) {
        uint32_t bf[2][4];
        LDSM4(bf[0][0], bf[0][1], bf[0][2], bf[0][3], bb + ks*32);
        LDSM4(bf[1][0], bf[1][1], bf[1][2], bf[1][3], bb + 16*144 + ks*32);
        #pragma unroll
        for (int mt = 0; mt < 4; mt++) {
            uint32_t af[4];
            LDSM4(af[0], af[1], af[2], af[3], ab + mt*(16*APITCH_B) + ks*32);
            #pragma unroll
            for (int nt = 0; nt < 4; nt++)
                mma16816(acc[mt][nt], af,
                         bf[nt >> 1][(nt & 1)*2], bf[nt >> 1][(nt & 1)*2 + 1]);
        }
    }
}

__device__ __forceinline__ void zero_acc2(float acc[2][4][4])
{
    #pragma unroll
    for (int mt = 0; mt < 2; mt++)
        #pragma unroll
        for (int nt = 0; nt < 4; nt++)
            #pragma unroll
            for (int j = 0; j < 4; j++) acc[mt][nt][j] = 0.f;
}
__device__ __forceinline__ void zero_acc4(float acc[4][4][4])
{
    #pragma unroll
    for (int mt = 0; mt < 4; mt++)
        #pragma unroll
        for (int nt = 0; nt < 4; nt++)
            #pragma unroll
            for (int j = 0; j < 4; j++) acc[mt][nt][j] = 0.f;
}

// ---------------- LN helpers ----------------
__device__ __forceinline__ void ln_stats8(const float2* rowred, float& mu, float& rs)
{
    float S = 0.f, Q = 0.f;
    #pragma unroll
    for (int i = 0; i < 8; i++) { float2 e = rowred[i]; S += e.x; Q += e.y; }
    mu = S * (1.f/DM);
    float var = Q * (1.f/DM) - mu*mu;
    rs = rsqrtf(var + 1e-5f);
}

// ---------------- qkvmma v2: 128 rows/CTA, fused LN ----------------
__global__ void __launch_bounds__(512) qkvmma_kernel(
    const float* __restrict__ features, const float* __restrict__ b_pre,
    const float* __restrict__ gdm, const float* __restrict__ bdm)
{
    extern __shared__ char smemc[];
    __shared__ float2 red[128][8];
    uint32_t sA = smem_u32(smemc);
    uint32_t sB = sA + ABYTES128;
    const int tid = threadIdx.x, lane = tid & 31, w = tid >> 5;
    const int wn = w & 7, wm2 = w >> 3;
    const int p0 = blockIdx.x * 128;

    // chunk0 = Wpre (row stride 64), chunk1 = WQ kt0
    {
        #pragma unroll
        for (int i = 0; i < 4; i++) {
            int ch = tid + i*512; int r = ch >> 3, c = ch & 7;
            CP16(sB + r*144 + c*16, g_Wpreh + r*64 + c*8);
        }
        CP_COMMIT();
        load_w512(sB, g_WQh, 0, 1, tid); CP_COMMIT();
    }

    // features -> A fp16 (128 rows x 64 k)
    for (int ch = tid; ch < 128*32; ch += 512) {
        int r = ch >> 5, c2 = ch & 31;
        float2 v = *(const float2*)&features[(size_t)(p0 + r)*DP + c2*2];
        *(half2*)(smemc + (size_t)r*APITCH_B + c2*4) = __floats2half2_rn(v.x, v.y);
    }

    const uint32_t aBase = sA + (uint32_t)(wm2*64 + (lane & 15))*APITCH_B + (lane >> 4)*16;
    const uint32_t bAddr = sB + (uint32_t)(wn*32 + ((lane >> 4) & 1)*8 + (lane & 7))*144
                              + ((lane >> 3) & 1)*16;

    float acc[4][4][4];

    // ---- stage 0: inp = feat @ Wpre^T + b_pre (K=64, chunk0) ----
    zero_acc4(acc);
    CP_WAIT1(); __syncthreads();
    mma_tile128(aBase, bAddr, acc);
    __syncthreads();
    load_w512(sB, g_WQh, 1, 0, tid); CP_COMMIT();   // chunk2
    {
        const int r0b = lane >> 2;
        #pragma unroll
        for (int mt = 0; mt < 4; mt++) {
            int gmt = wm2*4 + mt;
            int r0 = gmt*16 + r0b, r1 = r0 + 8;
            #pragma unroll
            for (int nt = 0; nt < 4; nt++) {
                int col = wn*32 + nt*8 + (lane & 3)*2;
                float b0 = b_pre[col], b1 = b_pre[col+1];
                *(half2*)(smemc + (size_t)r0*APITCH_B + col*2) =
                    __floats2half2_rn(acc[mt][nt][0] + b0, acc[mt][nt][1] + b1);
                *(half2*)(smemc + (size_t)r1*APITCH_B + col*2) =
                    __floats2half2_rn(acc[mt][nt][2] + b0, acc[mt][nt][3] + b1);
            }
        }
    }

    // ---- stages 1..3: Q/K/V, K=256 ----
    const __half* Ws[3] = { g_WQh, g_WKh, g_WVh };
    float* outs[3] = { g_Q, g_Kf, g_Vf };
    for (int s = 0; s < 3; s++) {
        zero_acc4(acc);
        for (int kt = 0; kt < 4; kt++) {
            int c = 1 + s*4 + kt;
            if (c == 12) { CP_WAIT0(); } else { CP_WAIT1(); }
            __syncthreads();
            mma_tile128(aBase + kt*128, bAddr + (uint32_t)(c & 1)*BBYTES, acc);
            __syncthreads();
            int nc = c + 2;
            if (nc <= 12) {
                int ns = (nc - 1) >> 2, nkt = (nc - 1) & 3;
                load_w512(sB, Ws[ns], nkt, nc & 1, tid);
                CP_COMMIT();
            }
        }
        // fused LN -> fp32
        {
            const int r0b = lane >> 2;
            #pragma unroll
            for (int mt = 0; mt < 4; mt++) {
                int gmt = wm2*4 + mt;
                int r0 = gmt*16 + r0b, r1 = r0 + 8;
                float s0=0.f, q0=0.f, s1=0.f, q1=0.f;
                #pragma unroll
                for (int nt = 0; nt < 4; nt++) {
                    float a0=acc[mt][nt][0], a1=acc[mt][nt][1];
                    float a2=acc[mt][nt][2], a3=acc[mt][nt][3];
                    s0 += a0+a1; q0 += a0*a0+a1*a1;
                    s1 += a2+a3; q1 += a2*a2+a3*a3;
                }
                #pragma unroll
                for (int o = 1; o < 4; o <<= 1) {
                    s0 += __shfl_xor_sync(~0u, s0, o); q0 += __shfl_xor_sync(~0u, q0, o);
                    s1 += __shfl_xor_sync(~0u, s1, o); q1 += __shfl_xor_sync(~0u, q1, o);
                }
                if ((lane & 3) == 0) {
                    red[r0][wn] = make_float2(s0, q0);
                    red[r1][wn] = make_float2(s1, q1);
                }
            }
        }
        __syncthreads();
        float* outg = outs[s];
        {
            const int r0b = lane >> 2;
            #pragma unroll
            for (int mt = 0; mt < 4; mt++) {
                int gmt = wm2*4 + mt;
                int r0 = gmt*16 + r0b, r1 = r0 + 8;
                float mu0, rs0, mu1, rs1;
                ln_stats8(red[r0], mu0, rs0);
                ln_stats8(red[r1], mu1, rs1);
                #pragma unroll
                for (int nt = 0; nt < 4; nt++) {
                    int col = wn*32 + nt*8 + (lane & 3)*2;
                    float g0 = gdm[col], g1 = gdm[col+1];
                    float b0 = bdm[col], b1 = bdm[col+1];
                    *(float2*)&outg[(size_t)(p0+r0)*DM + col] = make_float2(
                        (acc[mt][nt][0]-mu0)*rs0*g0 + b0, (acc[mt][nt][1]-mu0)*rs0*g1 + b1);
                    *(float2*)&outg[(size_t)(p0+r1)*DM + col] = make_float2(
                        (acc[mt][nt][2]-mu1)*rs1*g0 + b0, (acc[mt][nt][3]-mu1)*rs1*g1 + b1);
                }
            }
        }
        __syncthreads();   // red reuse
    }
}

// ---------------- mega kernel (exact R10 config: 128 rows, 512 thr, U smem) ---
__global__ void __launch_bounds__(512) mega_kernel(
    const float* __restrict__ xyz, const float* __restrict__ Wp1)
{
    extern __shared__ char smemc[];
    uint32_t sA = smem_u32(smemc);
    uint32_t sB = sA + BOFF;

    const int tid  = threadIdx.x;
    const int lane = tid & 31, w = tid >> 5;
    const int wn = w & 7, wm2 = w >> 3;
    const int m0    = blockIdx.x * 128;
    const int pbase = m0 >> 4;
    const int bq    = pbase >> 12;

    __shared__ float rel3[128][3];
    __shared__ int   idxs[128];

    const __half* Ws[3] = { g_Wp2h, g_Wa1h, g_Wa2h };

    load_w512(sB, g_Wp2h, 0, 0, tid); CP_COMMIT();
    load_w512(sB, g_Wp2h, 1, 1, tid); CP_COMMIT();

    if (tid < 128) {
        int m  = m0 + tid;
        int pt = m >> 4;
        int n  = pt & (NN - 1);
        int id = g_idx[(size_t)pt*KK + (m & 15)];
        idxs[tid] = id;
        const float* xb = xyz + (size_t)bq*NN*3;
        rel3[tid][0] = xb[n*3 + 0] - xb[id*3 + 0];
        rel3[tid][1] = xb[n*3 + 1] - xb[id*3 + 1];
        rel3[tid][2] = xb[n*3 + 2] - xb[id*3 + 2];
    }
    __syncthreads();

    {
        int c0 = (tid & 127)*2;
        int j0 = (tid >> 7)*32;
        float a0 = Wp1[c0*3+0], a1 = Wp1[c0*3+1], a2 = Wp1[c0*3+2];
        float d0 = Wp1[c0*3+3], d1 = Wp1[c0*3+4], d2 = Wp1[c0*3+5];
        #pragma unroll 8
        for (int j = j0; j < j0 + 32; j++) {
            float h0 = fmaf(a0, rel3[j][0], fmaf(a1, rel3[j][1], a2*rel3[j][2]));
            float h1 = fmaf(d0, rel3[j][0], fmaf(d1, rel3[j][1], d2*rel3[j][2]));
            *(half2*)(smemc + (size_t)j*APITCH_B + c0*2) =
                __floats2half2_rn(fmaxf(h0, 0.f), fmaxf(h1, 0.f));
        }
    }

    const uint32_t aBase = sA + (uint32_t)(wm2*64 + (lane & 15))*APITCH_B + (lane >> 4)*16;
    const uint32_t bAddr = sB + (uint32_t)(wn*32 + ((lane >> 4) & 1)*8 + (lane & 7))*144
                              + ((lane >> 3) & 1)*16;

    float acc[4][4][4];

    #pragma unroll 1
    for (int c = 0; c < 12; c++) {
        const int kt = c & 3;
        if (kt == 0) zero_acc4(acc);

        if (c >= 10) { CP_WAIT0(); } else { CP_WAIT1(); }
        __syncthreads();

        mma_tile128(aBase + kt*128, bAddr + (uint32_t)(c & 1)*BBYTES, acc);
        __syncthreads();

        if (c + 2 < 12) {
            int nc = c + 2;
            load_w512(sB, Ws[nc >> 2], nc & 3, c & 1, tid);
            CP_COMMIT();
        }

        if (kt == 3) {
            const int stage = c >> 2;
            const int r0b  = lane >> 2;
            const int colb = wn*32 + (lane & 3)*2;

            if (stage == 0) {
                #pragma unroll
                for (int mt = 0; mt < 4; mt++) {
                    int gmt = wm2*4 + mt;
                    int pt  = pbase + gmt;
                    int r0  = gmt*16 + r0b, r1 = r0 + 8;
                    const float* qp  = g_Q  + (size_t)pt*DM;
                    const float* k0p = g_Kf + ((size_t)(bq << 12) + idxs[r0])*DM;
                    const float* k1p = g_Kf + ((size_t)(bq << 12) + idxs[r1])*DM;
                    const float* v0p = g_Vf + ((size_t)(bq << 12) + idxs[r0])*DM;
                    const float* v1p = g_Vf + ((size_t)(bq << 12) + idxs[r1])*DM;
                    #pragma unroll
                    for (int nt = 0; nt < 4; nt++) {
                        int col = colb + nt*8;
                        float2 q  = *(const float2*)(qp  + col);
                        float2 ka = *(const float2*)(k0p + col);
                        float2 kb = *(const float2*)(k1p + col);
                        float2 va = *(const float2*)(v0p + col);
                        float2 vb = *(const float2*)(v1p + col);
                        float p00 = acc[mt][nt][0], p01 = acc[mt][nt][1];
                        float p10 = acc[mt][nt][2], p11 = acc[mt][nt][3];
                        *(half2*)(smemc + (size_t)r0*APITCH_B + col*2) =
                            __floats2half2_rn(q.x - ka.x + p00, q.y - ka.y + p01);
                        *(half2*)(smemc + (size_t)r1*APITCH_B + col*2) =
                            __floats2half2_rn(q.x - kb.x + p10, q.y - kb.y + p11);
                        *(half2*)(smemc + UOFF + (size_t)r0*APITCH_B + col*2) =
                            __floats2half2_rn(va.x + p00, va.y + p01);
                        *(half2*)(smemc + UOFF + (size_t)r1*APITCH_B + col*2) =
                            __floats2half2_rn(vb.x + p10, vb.y + p11);
                    }
                }
            } else if (stage == 1) {
                #pragma unroll
                for (int mt = 0; mt < 4; mt++) {
                    int gmt = wm2*4 + mt;
                    int r0  = gmt*16 + r0b, r1 = r0 + 8;
                    #pragma unroll
                    for (int nt = 0; nt < 4; nt++) {
                        int col = colb + nt*8;
                        *(half2*)(smemc + (size_t)r0*APITCH_B + col*2) =
                            __floats2half2_rn(fmaxf(acc[mt][nt][0], 0.f), fmaxf(acc[mt][nt][1], 0.f));
                        *(half2*)(smemc + (size_t)r1*APITCH_B + col*2) =
                            __floats2half2_rn(fmaxf(acc[mt][nt][2], 0.f), fmaxf(acc[mt][nt][3], 0.f));
                    }
                }
            } else {
                const float sc = 0.0625f;
                #pragma unroll
                for (int mt = 0; mt < 4; mt++) {
                    int gmt = wm2*4 + mt;
                    int pt  = pbase + gmt;
                    int r0  = gmt*16 + r0b, r1 = r0 + 8;
                    #pragma unroll
                    for (int nt = 0; nt < 4; nt++) {
                        int col = colb + nt*8;
                        float2 ua = __half22float2(
                            *(half2*)(smemc + UOFF + (size_t)r0*APITCH_B + col*2));
                        float2 ub = __half22float2(
                            *(half2*)(smemc + UOFF + (size_t)r1*APITCH_B + col*2));
                        float rout[2];
                        #pragma unroll
                        for (int p = 0; p < 2; p++) {
                            float x0 = acc[mt][nt][p]     * sc;
                            float x1 = acc[mt][nt][2 + p] * sc;
                            float mx = fmaxf(x0, x1);
                            #pragma unroll
                            for (int o = 4; o < 32; o <<= 1)
                                mx = fmaxf(mx, __shfl_xor_sync(0xffffffffu, mx, o));
                            float e0 = __expf(x0 - mx), e1 = __expf(x1 - mx);
                            float s  = e0 + e1;
                            float uu0 = p ? ua.y : ua.x;
                            float uu1 = p ? ub.y : ub.x;
                            float ww = e0*uu0 + e1*uu1;
                            #pragma unroll
                            for (int o = 4; o < 32; o <<= 1) {
                                s  += __shfl_xor_sync(0xffffffffu, s , o);
                                ww += __shfl_xor_sync(0xffffffffu, ww, o);
                            }
                            rout[p] = ww / s;
                        }
                        if (lane < 4)
                            *(float2*)&g_res[(size_t)pt*DM + col] = make_float2(rout[0], rout[1]);
                    }
                }
            }
        }
    }
}

// ---------------- final via HMMA (unchanged, 64 rows) ----------------
__global__ void __launch_bounds__(512) finalmma_kernel(
    const float* __restrict__ features, const float* __restrict__ b_post,
    const float* __restrict__ gdm, const float* __restrict__ bdm,
    const float* __restrict__ gdp, const float* __restrict__ bdp,
    float* __restrict__ out)
{
    extern __shared__ char smemc[];
    __shared__ float2 red[64][8];
    uint32_t sA = smem_u32(smemc);
    uint32_t sB = sA + ABYTES64;
    const int tid = threadIdx.x, lane = tid & 31, w = tid >> 5;
    const int wn = w & 7, wm2 = w >> 3;
    const int p0 = blockIdx.x * 64;

    load_w512(sB, g_Wprojh, 0, 0, tid); CP_COMMIT();
    load_w512(sB, g_Wprojh, 1, 1, tid); CP_COMMIT();

    for (int ch = tid; ch < 64*128; ch += 512) {
        int r = ch >> 7, c2 = ch & 127;
        float2 v = *(const float2*)&g_res[(size_t)(p0 + r)*DM + c2*2];
        *(half2*)(smemc + (size_t)r*APITCH_B + c2*4) = __floats2half2_rn(v.x, v.y);
    }

    const uint32_t aAddr = sA + (uint32_t)(wm2*32 + (lane & 15))*APITCH_B + (lane >> 4)*16;
    const uint32_t bAddr = sB + (uint32_t)(wn*32 + ((lane >> 4) & 1)*8 + (lane & 7))*144
                              + ((lane >> 3) & 1)*16;

    float acc[2][4][4];
    zero_acc2(acc);
    for (int kt = 0; kt < 4; kt++) {
        if (kt == 3) { CP_WAIT0(); } else { CP_WAIT1(); }
        __syncthreads();
        mma_tile512(aAddr + kt*128, bAddr + (uint32_t)(kt & 1)*BBYTES, acc);
        __syncthreads();
        if (kt + 2 < 4) { load_w512(sB, g_Wprojh, kt + 2, kt & 1, tid); CP_COMMIT(); }
    }

    // LN reduce
    #pragma unroll
    for (int mt = 0; mt < 2; mt++) {
        int gmt = wm2*2 + mt;
        int r0 = gmt*16 + (lane >> 2), r1 = r0 + 8;
        float s0=0.f, q0=0.f, s1=0.f, q1=0.f;
        #pragma unroll
        for (int nt = 0; nt < 4; nt++) {
            float a0=acc[mt][nt][0], a1=acc[mt][nt][1];
            float a2=acc[mt][nt][2], a3=acc[mt][nt][3];
            s0 += a0+a1; q0 += a0*a0+a1*a1;
            s1 += a2+a3; q1 += a2*a2+a3*a3;
        }
        #pragma unroll
        for (int o = 1; o < 4; o <<= 1) {
            s0 += __shfl_xor_sync(~0u, s0, o); q0 += __shfl_xor_sync(~0u, q0, o);
            s1 += __shfl_xor_sync(~0u, s1, o); q1 += __shfl_xor_sync(~0u, q1, o);
        }
        if ((lane & 3) == 0) {
            red[r0][wn] = make_float2(s0, q0);
            red[r1][wn] = make_float2(s1, q1);
        }
    }
    __syncthreads();

    #pragma unroll
    for (int mt = 0; mt < 2; mt++) {
        int gmt = wm2*2 + mt;
        int r0 = gmt*16 + (lane >> 2), r1 = r0 + 8;
        float mu0, rs0, mu1, rs1;
        ln_stats8(red[r0], mu0, rs0);
        ln_stats8(red[r1], mu1, rs1);
        #pragma unroll
        for (int nt = 0; nt < 4; nt++) {
            int col = wn*32 + nt*8 + (lane & 3)*2;
            float g0 = gdm[col], g1 = gdm[col+1];
            float b0 = bdm[col], b1 = bdm[col+1];
            *(half2*)(smemc + (size_t)r0*APITCH_B + col*2) = __floats2half2_rn(
                (acc[mt][nt][0]-mu0)*rs0*g0 + b0, (acc[mt][nt][1]-mu0)*rs0*g1 + b1);
            *(half2*)(smemc + (size_t)r1*APITCH_B + col*2) = __floats2half2_rn(
                (acc[mt][nt][2]-mu1)*rs1*g0 + b0, (acc[mt][nt][3]-mu1)*rs1*g1 + b1);
        }
    }
    __syncthreads();

    const int po = tid & 63, rg = tid >> 6;
    float o[8];
    #pragma unroll
    for (int i = 0; i < 8; i++) o[i] = b_post[po];
    for (int j2 = 0; j2 < 128; j2++) {
        float w0 = g_WpostT[(2*j2)*DP + po];
        float w1 = g_WpostT[(2*j2+1)*DP + po];
        #pragma unroll
        for (int i = 0; i < 8; i++) {
            int r = rg*8 + i;
            half2 zz = *(const half2*)(smemc + (size_t)r*APITCH_B + j2*4);
            float2 zf = __half22float2(zz);
            o[i] = fmaf(w0, zf.x, fmaf(w1, zf.y, o[i]));
        }
    }

    float* obuf = (float*)(smemc + ABYTES64);
    #pragma unroll
    for (int i = 0; i < 8; i++) obuf[(rg*8 + i)*68 + po] = o[i];
    __syncthreads();

    #pragma unroll
    for (int i = 0; i < 4; i++) {
        int row = w*4 + i;
        float x0 = obuf[row*68 + lane], x1 = obuf[row*68 + 32 + lane];
        float s = x0 + x1, s2 = x0*x0 + x1*x1;
        warp_bfly2(s, s2);
        float mu = s*(1.f/DP), var = s2*(1.f/DP) - mu*mu;
        float rs = rsqrtf(var + 1e-5f);
        size_t base = (size_t)(p0 + row)*DP;
        out[base + lane]      = (x0-mu)*rs*gdp[lane]      + bdp[lane]      + features[base + lane];
        out[base + 32 + lane] = (x1-mu)*rs*gdp[32 + lane] + bdp[32 + lane] + features[base + 32 + lane];
    }
}

// ---------------- launch (knn overlapped on a side stream) ----------------
extern "C" void kernel_launch(void* const* d_in, const int* in_sizes, int n_in,
                              void* d_out, int out_size)
{
    const float* xyz      = (const float*)d_in[0];
    const float* features = (const float*)d_in[1];
    const float* W_pre    = (const float*)d_in[2];
    const float* b_pre    = (const float*)d_in[3];
    const float* W_post   = (const float*)d_in[4];
    const float* b_post   = (const float*)d_in[5];
    const float* Wp1      = (const float*)d_in[6];
    const float* Wp2      = (const float*)d_in[7];
    const float* Wa1      = (const float*)d_in[8];
    const float* Wa2      = (const float*)d_in[9];
    const float* WQ       = (const float*)d_in[10];
    const float* WK       = (const float*)d_in[11];
    const float* WV       = (const float*)d_in[12];
    const float* Wproj    = (const float*)d_in[13];
    const float* g_dm     = (const float*)d_in[14];
    const float* b_dm     = (const float*)d_in[15];
    const float* g_dp     = (const float*)d_in[16];
    const float* b_dp     = (const float*)d_in[17];
    float* out = (float*)d_out;

    static cudaStream_t s_knn = nullptr;
    static cudaEvent_t ev_fork = nullptr, ev_knn = nullptr;
    if (!s_knn) {
        cudaStreamCreateWithFlags(&s_knn, cudaStreamNonBlocking);
        cudaEventCreateWithFlags(&ev_fork, cudaEventDisableTiming);
        cudaEventCreateWithFlags(&ev_knn,  cudaEventDisableTiming);
        cudaFuncSetAttribute(knn_kernel, cudaFuncAttributeMaxDynamicSharedMemorySize,
                             NN * (int)sizeof(float4));
        cudaFuncSetAttribute(mega_kernel,     cudaFuncAttributeMaxDynamicSharedMemorySize, MEGA_SMEM);
        cudaFuncSetAttribute(qkvmma_kernel,   cudaFuncAttributeMaxDynamicSharedMemorySize, QKV_SMEM);
        cudaFuncSetAttribute(finalmma_kernel, cudaFuncAttributeMaxDynamicSharedMemorySize, FIN_SMEM);
    }

    // fork: knn runs on the side stream concurrently with prep+qkvmma
    cudaEventRecord(ev_fork, 0);
    cudaStreamWaitEvent(s_knn, ev_fork, 0);
    knn_kernel<<<BB*64, 256, NN*sizeof(float4), s_knn>>>(xyz);
    cudaEventRecord(ev_knn, s_knn);

    prep_kernel<<<256, 256>>>(W_pre, WQ, WK, WV, Wproj, W_post, Wp2, Wa1, Wa2);
    qkvmma_kernel<<<NPTS/128, 512, QKV_SMEM>>>(features, b_pre, g_dm, b_dm);

    // join: mega needs g_idx from knn
    cudaStreamWaitEvent(0, ev_knn, 0);
    mega_kernel<<<MTOT/128, 512, MEGA_SMEM>>>(xyz, Wp1);

    finalmma_kernel<<<NPTS/64, 512, FIN_SMEM>>>(features, b_post, g_dm, b_dm,
                                                g_dp, b_dp, out);
}

// round 13
// speedup vs baseline: 1.7547x; 1.0871x over previous
#include <cuda_runtime.h>
#include <cuda_fp16.h>
#include <cstddef>
#include <cstdint>

#define BB 4
#define NN 4096
#define KK 16
#define DP 64
#define DM 256
#define NPTS (BB*NN)
#define MTOT (NPTS*KK)

// ---------------- device-global scratch (no allocs allowed) ----------------
__device__ __half g_Wposth[DP*DM];   // [n=64][k=256]
__device__ __half g_Wpreh[DM*DP];    // [n=256][k=64]
__device__ __half g_WQh [DM*DM];     // [n][k]
__device__ __half g_WKh [DM*DM];
__device__ __half g_WVh [DM*DM];
__device__ __half g_Wprojh[DM*DM];
__device__ __half g_Wp2h[DM*DM];
__device__ __half g_Wa1h[DM*DM];
__device__ __half g_Wa2h[DM*DM];
__device__ __half g_Qh [NPTS*DM];
__device__ __half g_Kh [NPTS*DM];
__device__ __half g_Vh [NPTS*DM];
__device__ int   g_idx[NPTS*KK];
__device__ float g_res[(size_t)NPTS*DM];

// ---------------- helpers ----------------
__device__ __forceinline__ uint32_t smem_u32(const void* p) {
    uint32_t a;
    asm("{ .reg .u64 t; cvta.to.shared.u64 t, %1; cvt.u32.u64 %0, t; }" : "=r"(a) : "l"(p));
    return a;
}
#define CP16(dst, src) asm volatile("cp.async.cg.shared.global [%0], [%1], 16;" :: "r"(dst), "l"(src) : "memory")
#define CP_COMMIT()    asm volatile("cp.async.commit_group;" ::: "memory")
#define CP_WAIT1()     asm volatile("cp.async.wait_group 1;" ::: "memory")
#define CP_WAIT0()     asm volatile("cp.async.wait_group 0;" ::: "memory")
#define LDSM4(r0,r1,r2,r3,a) \
    asm volatile("ldmatrix.sync.aligned.m8n8.x4.shared.b16 {%0,%1,%2,%3}, [%4];" \
                 : "=r"(r0),"=r"(r1),"=r"(r2),"=r"(r3) : "r"(a))

__device__ __forceinline__ void mma16816(float* c, const uint32_t* a, uint32_t b0, uint32_t b1) {
    asm volatile("mma.sync.aligned.m16n8k16.row.col.f32.f16.f16.f32 "
        "{%0,%1,%2,%3}, {%4,%5,%6,%7}, {%8,%9}, {%0,%1,%2,%3};"
        : "+f"(c[0]), "+f"(c[1]), "+f"(c[2]), "+f"(c[3])
        : "r"(a[0]), "r"(a[1]), "r"(a[2]), "r"(a[3]), "r"(b0), "r"(b1));
}

#define APITCH_B 528
#define ABYTES128 (128*APITCH_B)           // 67584
#define BBYTES    (256*144)                // 36864
#define QKV_SMEM  (ABYTES128 + 2*BBYTES)   // 141312 (qkvmma + finalmma)
#define UOFF      ABYTES128
#define BOFF      (2*ABYTES128)
#define MEGA_SMEM (2*ABYTES128 + 2*BBYTES) // 208896

// ---------------- weight prep ----------------
__global__ void prep_kernel(const float* __restrict__ W_pre,
                            const float* __restrict__ WQ,  const float* __restrict__ WK,
                            const float* __restrict__ WV,  const float* __restrict__ Wproj,
                            const float* __restrict__ W_post,
                            const float* __restrict__ Wp2, const float* __restrict__ Wa1,
                            const float* __restrict__ Wa2)
{
    int t = blockIdx.x * blockDim.x + threadIdx.x;
    if (t < DM*DP) {
        g_Wpreh[t]  = __float2half_rn(W_pre[t]);
        g_Wposth[t] = __float2half_rn(W_post[t]);   // [64][256] already n-by-k
    }
    if (t < DM*DM) {
        g_WQh  [t] = __float2half_rn(WQ[t]);
        g_WKh  [t] = __float2half_rn(WK[t]);
        g_WVh  [t] = __float2half_rn(WV[t]);
        g_Wprojh[t] = __float2half_rn(Wproj[t]);
        g_Wp2h[t] = __float2half_rn(Wp2[t]);
        g_Wa1h[t] = __float2half_rn(Wa1[t]);
        g_Wa2h[t] = __float2half_rn(Wa2[t]);
    }
}

// ---------------- kNN v3 (unchanged) ----------------
__device__ __forceinline__ void ins16(float* bd, int* bi, float d, int m)
{
    #pragma unroll
    for (int i = 15; i >= 1; i--) {
        bool c1 = d < bd[i-1];
        bool c2 = d < bd[i];
        float nb = c1 ? bd[i-1] : (c2 ? d : bd[i]);
        int   ni = c1 ? bi[i-1] : (c2 ? m : bi[i]);
        bd[i] = nb; bi[i] = ni;
    }
    if (d < bd[0]) { bi[0] = m; bd[0] = d; }
}

__global__ void __launch_bounds__(256) knn_kernel(const float* __restrict__ xyz)
{
    extern __shared__ float4 pts[];
    __shared__ float md[64][3][16];
    __shared__ int   mi[64][3][16];

    int b     = blockIdx.x >> 6;
    int chunk = blockIdx.x & 63;
    const float* xb = xyz + (size_t)b * NN * 3;
    for (int m = threadIdx.x; m < NN; m += 256)
        pts[m] = make_float4(xb[m*3], xb[m*3+1], xb[m*3+2], 0.f);
    __syncthreads();

    int qloc = threadIdx.x & 63;
    int sub  = threadIdx.x >> 6;
    int qi   = chunk*64 + qloc;
    float4 qp = pts[qi];

    float bd[16]; int bi[16];
    #pragma unroll
    for (int i = 0; i < 16; i++) { bd[i] = 3.4e38f; bi[i] = 0; }

    int base = sub * 1024;
    #pragma unroll 2
    for (int m = base; m < base + 1024; m += 2) {
        float4 p0 = pts[m], p1 = pts[m+1];
        float dx0 = qp.x-p0.x, dy0 = qp.y-p0.y, dz0 = qp.z-p0.z;
        float dx1 = qp.x-p1.x, dy1 = qp.y-p1.y, dz1 = qp.z-p1.z;
        float d0 = fmaf(dx0,dx0, fmaf(dy0,dy0, dz0*dz0));
        float d1 = fmaf(dx1,dx1, fmaf(dy1,dy1, dz1*dz1));
        if (d0 < bd[15]) ins16(bd, bi, d0, m);
        if (d1 < bd[15]) ins16(bd, bi, d1, m+1);
    }

    if (sub) {
        #pragma unroll
        for (int i = 0; i < 16; i++) { md[qloc][sub-1][i] = bd[i]; mi[qloc][sub-1][i] = bi[i]; }
    }
    __syncthreads();
    if (sub == 0) {
        #pragma unroll
        for (int l = 0; l < 3; l++) {
            #pragma unroll
            for (int i = 0; i < 16; i++) {
                float d = md[qloc][l][i];
                if (d < bd[15]) ins16(bd, bi, d, mi[qloc][l][i]);
            }
        }
        #pragma unroll
        for (int i = 0; i < 16; i++)
            g_idx[(size_t)(b*NN + qi)*KK + i] = bi[i];
    }
}

// ---------------- shared MMA helpers ----------------
__device__ __forceinline__ void load_w512(uint32_t sB, const __half* __restrict__ W,
                                          int kt, int buf, int tid)
{
    uint32_t base = sB + (uint32_t)buf*BBYTES;
    #pragma unroll
    for (int i = 0; i < 4; i++) {
        int ch = tid + i*512;
        int r = ch >> 3, c = ch & 7;
        CP16(base + r*144 + c*16, W + (size_t)r*256 + kt*64 + c*8);
    }
}

// Wpost chunk: 64 rows x 64 k (128 B), one CP16 per thread
__device__ __forceinline__ void load_wpost(uint32_t sB, int kt, int buf, int tid)
{
    uint32_t base = sB + (uint32_t)buf*BBYTES;
    int r = tid >> 3, c = tid & 7;
    CP16(base + r*144 + c*16, g_Wposth + (size_t)r*256 + kt*64 + c*8);
}

// 128-row tile: 4 m-tiles per warp
__device__ __forceinline__ void mma_tile128(uint32_t ab, uint32_t bb, float acc[4][4][4])
{
    #pragma unroll
    for (int ks = 0; ks < 4; ks++) {
        uint32_t bf[2][4];
        LDSM4(bf[0][0], bf[0][1], bf[0][2], bf[0][3], bb + ks*32);
        LDSM4(bf[1][0], bf[1][1], bf[1][2], bf[1][3], bb + 16*144 + ks*32);
        #pragma unroll
        for (int mt = 0; mt < 4; mt++) {
            uint32_t af[4];
            LDSM4(af[0], af[1], af[2], af[3], ab + mt*(16*APITCH_B) + ks*32);
            #pragma unroll
            for (int nt = 0; nt < 4; nt++)
                mma16816(acc[mt][nt], af,
                         bf[nt >> 1][(nt & 1)*2], bf[nt >> 1][(nt & 1)*2 + 1]);
        }
    }
}

__device__ __forceinline__ void zero_acc4(float acc[4][4][4])
{
    #pragma unroll
    for (int mt = 0; mt < 4; mt++)
        #pragma unroll
        for (int nt = 0; nt < 4; nt++)
            #pragma unroll
            for (int j = 0; j < 4; j++) acc[mt][nt][j] = 0.f;
}

__device__ __forceinline__ void ln_stats8(const float2* rowred, float inv, float& mu, float& rs)
{
    float S = 0.f, Q = 0.f;
    #pragma unroll
    for (int i = 0; i < 8; i++) { float2 e = rowred[i]; S += e.x; Q += e.y; }
    mu = S * inv;
    float var = Q * inv - mu*mu;
    rs = rsqrtf(var + 1e-5f);
}

// ---------------- qkvmma: 128 rows/CTA, fused LN, fp16 output ----------------
__global__ void __launch_bounds__(512) qkvmma_kernel(
    const float* __restrict__ features, const float* __restrict__ b_pre,
    const float* __restrict__ gdm, const float* __restrict__ bdm)
{
    extern __shared__ char smemc[];
    __shared__ float2 red[128][8];
    uint32_t sA = smem_u32(smemc);
    uint32_t sB = sA + ABYTES128;
    const int tid = threadIdx.x, lane = tid & 31, w = tid >> 5;
    const int wn = w & 7, wm2 = w >> 3;
    const int p0 = blockIdx.x * 128;

    {
        #pragma unroll
        for (int i = 0; i < 4; i++) {
            int ch = tid + i*512; int r = ch >> 3, c = ch & 7;
            CP16(sB + r*144 + c*16, g_Wpreh + r*64 + c*8);
        }
        CP_COMMIT();
        load_w512(sB, g_WQh, 0, 1, tid); CP_COMMIT();
    }

    for (int ch = tid; ch < 128*32; ch += 512) {
        int r = ch >> 5, c2 = ch & 31;
        float2 v = *(const float2*)&features[(size_t)(p0 + r)*DP + c2*2];
        *(half2*)(smemc + (size_t)r*APITCH_B + c2*4) = __floats2half2_rn(v.x, v.y);
    }

    const uint32_t aBase = sA + (uint32_t)(wm2*64 + (lane & 15))*APITCH_B + (lane >> 4)*16;
    const uint32_t bAddr = sB + (uint32_t)(wn*32 + ((lane >> 4) & 1)*8 + (lane & 7))*144
                              + ((lane >> 3) & 1)*16;

    float acc[4][4][4];

    // stage 0: inp = feat @ Wpre^T + b_pre
    zero_acc4(acc);
    CP_WAIT1(); __syncthreads();
    mma_tile128(aBase, bAddr, acc);
    __syncthreads();
    load_w512(sB, g_WQh, 1, 0, tid); CP_COMMIT();
    {
        const int r0b = lane >> 2;
        #pragma unroll
        for (int mt = 0; mt < 4; mt++) {
            int gmt = wm2*4 + mt;
            int r0 = gmt*16 + r0b, r1 = r0 + 8;
            #pragma unroll
            for (int nt = 0; nt < 4; nt++) {
                int col = wn*32 + nt*8 + (lane & 3)*2;
                float b0 = b_pre[col], b1 = b_pre[col+1];
                *(half2*)(smemc + (size_t)r0*APITCH_B + col*2) =
                    __floats2half2_rn(acc[mt][nt][0] + b0, acc[mt][nt][1] + b1);
                *(half2*)(smemc + (size_t)r1*APITCH_B + col*2) =
                    __floats2half2_rn(acc[mt][nt][2] + b0, acc[mt][nt][3] + b1);
            }
        }
    }

    const __half* Ws[3] = { g_WQh, g_WKh, g_WVh };
    __half* outs[3] = { g_Qh, g_Kh, g_Vh };
    for (int s = 0; s < 3; s++) {
        zero_acc4(acc);
        for (int kt = 0; kt < 4; kt++) {
            int c = 1 + s*4 + kt;
            if (c == 12) { CP_WAIT0(); } else { CP_WAIT1(); }
            __syncthreads();
            mma_tile128(aBase + kt*128, bAddr + (uint32_t)(c & 1)*BBYTES, acc);
            __syncthreads();
            int nc = c + 2;
            if (nc <= 12) {
                int ns = (nc - 1) >> 2, nkt = (nc - 1) & 3;
                load_w512(sB, Ws[ns], nkt, nc & 1, tid);
                CP_COMMIT();
            }
        }
        // fused LN -> fp16
        {
            const int r0b = lane >> 2;
            #pragma unroll
            for (int mt = 0; mt < 4; mt++) {
                int gmt = wm2*4 + mt;
                int r0 = gmt*16 + r0b, r1 = r0 + 8;
                float s0=0.f, q0=0.f, s1=0.f, q1=0.f;
                #pragma unroll
                for (int nt = 0; nt < 4; nt++) {
                    float a0=acc[mt][nt][0], a1=acc[mt][nt][1];
                    float a2=acc[mt][nt][2], a3=acc[mt][nt][3];
                    s0 += a0+a1; q0 += a0*a0+a1*a1;
                    s1 += a2+a3; q1 += a2*a2+a3*a3;
                }
                #pragma unroll
                for (int o = 1; o < 4; o <<= 1) {
                    s0 += __shfl_xor_sync(~0u, s0, o); q0 += __shfl_xor_sync(~0u, q0, o);
                    s1 += __shfl_xor_sync(~0u, s1, o); q1 += __shfl_xor_sync(~0u, q1, o);
                }
                if ((lane & 3) == 0) {
                    red[r0][wn] = make_float2(s0, q0);
                    red[r1][wn] = make_float2(s1, q1);
                }
            }
        }
        __syncthreads();
        __half* outg = outs[s];
        {
            const int r0b = lane >> 2;
            #pragma unroll
            for (int mt = 0; mt < 4; mt++) {
                int gmt = wm2*4 + mt;
                int r0 = gmt*16 + r0b, r1 = r0 + 8;
                float mu0, rs0, mu1, rs1;
                ln_stats8(red[r0], 1.f/DM, mu0, rs0);
                ln_stats8(red[r1], 1.f/DM, mu1, rs1);
                #pragma unroll
                for (int nt = 0; nt < 4; nt++) {
                    int col = wn*32 + nt*8 + (lane & 3)*2;
                    float g0 = gdm[col], g1 = gdm[col+1];
                    float b0 = bdm[col], b1 = bdm[col+1];
                    *(half2*)&outg[(size_t)(p0+r0)*DM + col] = __floats2half2_rn(
                        (acc[mt][nt][0]-mu0)*rs0*g0 + b0, (acc[mt][nt][1]-mu0)*rs0*g1 + b1);
                    *(half2*)&outg[(size_t)(p0+r1)*DM + col] = __floats2half2_rn(
                        (acc[mt][nt][2]-mu1)*rs1*g0 + b0, (acc[mt][nt][3]-mu1)*rs1*g1 + b1);
                }
            }
        }
        __syncthreads();
    }
}

// ---------------- mega kernel (R10 config; fp16 gathers) ----------------
__global__ void __launch_bounds__(512) mega_kernel(
    const float* __restrict__ xyz, const float* __restrict__ Wp1)
{
    extern __shared__ char smemc[];
    uint32_t sA = smem_u32(smemc);
    uint32_t sB = sA + BOFF;

    const int tid  = threadIdx.x;
    const int lane = tid & 31, w = tid >> 5;
    const int wn = w & 7, wm2 = w >> 3;
    const int m0    = blockIdx.x * 128;
    const int pbase = m0 >> 4;
    const int bq    = pbase >> 12;

    __shared__ float rel3[128][3];
    __shared__ int   idxs[128];

    const __half* Ws[3] = { g_Wp2h, g_Wa1h, g_Wa2h };

    load_w512(sB, g_Wp2h, 0, 0, tid); CP_COMMIT();
    load_w512(sB, g_Wp2h, 1, 1, tid); CP_COMMIT();

    if (tid < 128) {
        int m  = m0 + tid;
        int pt = m >> 4;
        int n  = pt & (NN - 1);
        int id = g_idx[(size_t)pt*KK + (m & 15)];
        idxs[tid] = id;
        const float* xb = xyz + (size_t)bq*NN*3;
        rel3[tid][0] = xb[n*3 + 0] - xb[id*3 + 0];
        rel3[tid][1] = xb[n*3 + 1] - xb[id*3 + 1];
        rel3[tid][2] = xb[n*3 + 2] - xb[id*3 + 2];
    }
    __syncthreads();

    {
        int c0 = (tid & 127)*2;
        int j0 = (tid >> 7)*32;
        float a0 = Wp1[c0*3+0], a1 = Wp1[c0*3+1], a2 = Wp1[c0*3+2];
        float d0 = Wp1[c0*3+3], d1 = Wp1[c0*3+4], d2 = Wp1[c0*3+5];
        #pragma unroll 8
        for (int j = j0; j < j0 + 32; j++) {
            float h0 = fmaf(a0, rel3[j][0], fmaf(a1, rel3[j][1], a2*rel3[j][2]));
            float h1 = fmaf(d0, rel3[j][0], fmaf(d1, rel3[j][1], d2*rel3[j][2]));
            *(half2*)(smemc + (size_t)j*APITCH_B + c0*2) =
                __floats2half2_rn(fmaxf(h0, 0.f), fmaxf(h1, 0.f));
        }
    }

    const uint32_t aBase = sA + (uint32_t)(wm2*64 + (lane & 15))*APITCH_B + (lane >> 4)*16;
    const uint32_t bAddr = sB + (uint32_t)(wn*32 + ((lane >> 4) & 1)*8 + (lane & 7))*144
                              + ((lane >> 3) & 1)*16;

    float acc[4][4][4];

    #pragma unroll 1
    for (int c = 0; c < 12; c++) {
        const int kt = c & 3;
        if (kt == 0) zero_acc4(acc);

        if (c >= 10) { CP_WAIT0(); } else { CP_WAIT1(); }
        __syncthreads();

        mma_tile128(aBase + kt*128, bAddr + (uint32_t)(c & 1)*BBYTES, acc);
        __syncthreads();

        if (c + 2 < 12) {
            int nc = c + 2;
            load_w512(sB, Ws[nc >> 2], nc & 3, c & 1, tid);
            CP_COMMIT();
        }

        if (kt == 3) {
            const int stage = c >> 2;
            const int r0b  = lane >> 2;
            const int colb = wn*32 + (lane & 3)*2;

            if (stage == 0) {
                #pragma unroll
                for (int mt = 0; mt < 4; mt++) {
                    int gmt = wm2*4 + mt;
                    int pt  = pbase + gmt;
                    int r0  = gmt*16 + r0b, r1 = r0 + 8;
                    const __half* qp  = g_Qh + (size_t)pt*DM;
                    const __half* k0p = g_Kh + ((size_t)(bq << 12) + idxs[r0])*DM;
                    const __half* k1p = g_Kh + ((size_t)(bq << 12) + idxs[r1])*DM;
                    const __half* v0p = g_Vh + ((size_t)(bq << 12) + idxs[r0])*DM;
                    const __half* v1p = g_Vh + ((size_t)(bq << 12) + idxs[r1])*DM;
                    #pragma unroll
                    for (int nt = 0; nt < 4; nt++) {
                        int col = colb + nt*8;
                        float2 q  = __half22float2(*(const half2*)(qp  + col));
                        float2 ka = __half22float2(*(const half2*)(k0p + col));
                        float2 kb = __half22float2(*(const half2*)(k1p + col));
                        float2 va = __half22float2(*(const half2*)(v0p + col));
                        float2 vb = __half22float2(*(const half2*)(v1p + col));
                        float p00 = acc[mt][nt][0], p01 = acc[mt][nt][1];
                        float p10 = acc[mt][nt][2], p11 = acc[mt][nt][3];
                        *(half2*)(smemc + (size_t)r0*APITCH_B + col*2) =
                            __floats2half2_rn(q.x - ka.x + p00, q.y - ka.y + p01);
                        *(half2*)(smemc + (size_t)r1*APITCH_B + col*2) =
                            __floats2half2_rn(q.x - kb.x + p10, q.y - kb.y + p11);
                        *(half2*)(smemc + UOFF + (size_t)r0*APITCH_B + col*2) =
                            __floats2half2_rn(va.x + p00, va.y + p01);
                        *(half2*)(smemc + UOFF + (size_t)r1*APITCH_B + col*2) =
                            __floats2half2_rn(vb.x + p10, vb.y + p11);
                    }
                }
            } else if (stage == 1) {
                #pragma unroll
                for (int mt = 0; mt < 4; mt++) {
                    int gmt = wm2*4 + mt;
                    int r0  = gmt*16 + r0b, r1 = r0 + 8;
                    #pragma unroll
                    for (int nt = 0; nt < 4; nt++) {
                        int col = colb + nt*8;
                        *(half2*)(smemc + (size_t)r0*APITCH_B + col*2) =
                            __floats2half2_rn(fmaxf(acc[mt][nt][0], 0.f), fmaxf(acc[mt][nt][1], 0.f));
                        *(half2*)(smemc + (size_t)r1*APITCH_B + col*2) =
                            __floats2half2_rn(fmaxf(acc[mt][nt][2], 0.f), fmaxf(acc[mt][nt][3], 0.f));
                    }
                }
            } else {
                const float sc = 0.0625f;
                #pragma unroll
                for (int mt = 0; mt < 4; mt++) {
                    int gmt = wm2*4 + mt;
                    int pt  = pbase + gmt;
                    int r0  = gmt*16 + r0b, r1 = r0 + 8;
                    #pragma unroll
                    for (int nt = 0; nt < 4; nt++) {
                        int col = colb + nt*8;
                        float2 ua = __half22float2(
                            *(half2*)(smemc + UOFF + (size_t)r0*APITCH_B + col*2));
                        float2 ub = __half22float2(
                            *(half2*)(smemc + UOFF + (size_t)r1*APITCH_B + col*2));
                        float rout[2];
                        #pragma unroll
                        for (int p = 0; p < 2; p++) {
                            float x0 = acc[mt][nt][p]     * sc;
                            float x1 = acc[mt][nt][2 + p] * sc;
                            float mx = fmaxf(x0, x1);
                            #pragma unroll
                            for (int o = 4; o < 32; o <<= 1)
                                mx = fmaxf(mx, __shfl_xor_sync(0xffffffffu, mx, o));
                            float e0 = __expf(x0 - mx), e1 = __expf(x1 - mx);
                            float s  = e0 + e1;
                            float uu0 = p ? ua.y : ua.x;
                            float uu1 = p ? ub.y : ub.x;
                            float ww = e0*uu0 + e1*uu1;
                            #pragma unroll
                            for (int o = 4; o < 32; o <<= 1) {
                                s  += __shfl_xor_sync(0xffffffffu, s , o);
                                ww += __shfl_xor_sync(0xffffffffu, ww, o);
                            }
                            rout[p] = ww / s;
                        }
                        if (lane < 4)
                            *(float2*)&g_res[(size_t)pt*DM + col] = make_float2(rout[0], rout[1]);
                    }
                }
            }
        }
    }
}

// ---------------- finalmma v2: 128 rows, proj+LN+post(HMMA)+LN+residual ------
__global__ void __launch_bounds__(512) finalmma_kernel(
    const float* __restrict__ features, const float* __restrict__ b_post,
    const float* __restrict__ gdm, const float* __restrict__ bdm,
    const float* __restrict__ gdp, const float* __restrict__ bdp,
    float* __restrict__ out)
{
    extern __shared__ char smemc[];
    __shared__ float2 red[128][8];
    uint32_t sA = smem_u32(smemc);
    uint32_t sB = sA + ABYTES128;
    const int tid = threadIdx.x, lane = tid & 31, w = tid >> 5;
    const int wn = w & 7, wm2 = w >> 3;
    const int p0 = blockIdx.x * 128;

    load_w512(sB, g_Wprojh, 0, 0, tid); CP_COMMIT();
    load_w512(sB, g_Wprojh, 1, 1, tid); CP_COMMIT();

    // g_res -> A fp16 (128 rows x 256)
    for (int ch = tid; ch < 128*128; ch += 512) {
        int r = ch >> 7, c2 = ch & 127;
        float2 v = *(const float2*)&g_res[(size_t)(p0 + r)*DM + c2*2];
        *(half2*)(smemc + (size_t)r*APITCH_B + c2*4) = __floats2half2_rn(v.x, v.y);
    }

    const uint32_t aBase = sA + (uint32_t)(wm2*64 + (lane & 15))*APITCH_B + (lane >> 4)*16;
    const uint32_t bAddr = sB + (uint32_t)(wn*32 + ((lane >> 4) & 1)*8 + (lane & 7))*144
                              + ((lane >> 3) & 1)*16;
    const uint32_t bAddrP = sB + (uint32_t)(wn*8 + (lane & 7))*144 + (lane >> 3)*16;

    // ---- proj GEMM: chunks 0..3 ----
    float acc[4][4][4];
    zero_acc4(acc);
    for (int kt = 0; kt < 4; kt++) {
        CP_WAIT1();
        __syncthreads();
        mma_tile128(aBase + kt*128, bAddr + (uint32_t)(kt & 1)*BBYTES, acc);
        __syncthreads();
        int nc = kt + 2;
        if (nc < 4) load_w512(sB, g_Wprojh, nc, kt & 1, tid);
        else        load_wpost(sB, nc - 4, kt & 1, tid);
        CP_COMMIT();
    }

    // ---- LN(256) -> z fp16 back into A ----
    {
        const int r0b = lane >> 2;
        #pragma unroll
        for (int mt = 0; mt < 4; mt++) {
            int gmt = wm2*4 + mt;
            int r0 = gmt*16 + r0b, r1 = r0 + 8;
            float s0=0.f, q0=0.f, s1=0.f, q1=0.f;
            #pragma unroll
            for (int nt = 0; nt < 4; nt++) {
                float a0=acc[mt][nt][0], a1=acc[mt][nt][1];
                float a2=acc[mt][nt][2], a3=acc[mt][nt][3];
                s0 += a0+a1; q0 += a0*a0+a1*a1;
                s1 += a2+a3; q1 += a2*a2+a3*a3;
            }
            #pragma unroll
            for (int o = 1; o < 4; o <<= 1) {
                s0 += __shfl_xor_sync(~0u, s0, o); q0 += __shfl_xor_sync(~0u, q0, o);
                s1 += __shfl_xor_sync(~0u, s1, o); q1 += __shfl_xor_sync(~0u, q1, o);
            }
            if ((lane & 3) == 0) {
                red[r0][wn] = make_float2(s0, q0);
                red[r1][wn] = make_float2(s1, q1);
            }
        }
        __syncthreads();
        #pragma unroll
        for (int mt = 0; mt < 4; mt++) {
            int gmt = wm2*4 + mt;
            int r0 = gmt*16 + r0b, r1 = r0 + 8;
            float mu0, rs0, mu1, rs1;
            ln_stats8(red[r0], 1.f/DM, mu0, rs0);
            ln_stats8(red[r1], 1.f/DM, mu1, rs1);
            #pragma unroll
            for (int nt = 0; nt < 4; nt++) {
                int col = wn*32 + nt*8 + (lane & 3)*2;
                float g0 = gdm[col], g1 = gdm[col+1];
                float b0 = bdm[col], b1 = bdm[col+1];
                *(half2*)(smemc + (size_t)r0*APITCH_B + col*2) = __floats2half2_rn(
                    (acc[mt][nt][0]-mu0)*rs0*g0 + b0, (acc[mt][nt][1]-mu0)*rs0*g1 + b1);
                *(half2*)(smemc + (size_t)r1*APITCH_B + col*2) = __floats2half2_rn(
                    (acc[mt][nt][2]-mu1)*rs1*g0 + b0, (acc[mt][nt][3]-mu1)*rs1*g1 + b1);
            }
        }
    }
    // sync inside next loop head covers z visibility

    // ---- post GEMM via HMMA: chunks 4..7, N=64 (8 cols/warp) ----
    float accp[4][4];
    #pragma unroll
    for (int mt = 0; mt < 4; mt++)
        #pragma unroll
        for (int j = 0; j < 4; j++) accp[mt][j] = 0.f;

    for (int kt = 0; kt < 4; kt++) {
        int c = 4 + kt;
        if (c == 7) { CP_WAIT0(); } else { CP_WAIT1(); }
        __syncthreads();

        uint32_t ab = aBase + kt*128;
        uint32_t bb = bAddrP + (uint32_t)(c & 1)*BBYTES;
        #pragma unroll
        for (int ks2 = 0; ks2 < 2; ks2++) {
            uint32_t bfp[4];
            LDSM4(bfp[0], bfp[1], bfp[2], bfp[3], bb + ks2*64);
            #pragma unroll
            for (int sub = 0; sub < 2; sub++) {
                int ks = ks2*2 + sub;
                #pragma unroll
                for (int mt = 0; mt < 4; mt++) {
                    uint32_t af[4];
                    LDSM4(af[0], af[1], af[2], af[3], ab + mt*(16*APITCH_B) + ks*32);
                    mma16816(accp[mt], af, bfp[sub*2], bfp[sub*2 + 1]);
                }
            }
        }
        __syncthreads();
        if (kt + 2 < 4) { load_wpost(sB, kt + 2, c & 1, tid); CP_COMMIT(); }
    }

    // ---- + b_post, LN(64), + residual, write out ----
    {
        const int r0b = lane >> 2;
        const int col = wn*8 + (lane & 3)*2;
        float b0 = b_post[col], b1 = b_post[col+1];
        #pragma unroll
        for (int mt = 0; mt < 4; mt++) {
            accp[mt][0] += b0; accp[mt][1] += b1;
            accp[mt][2] += b0; accp[mt][3] += b1;
        }
        // partial sums per (row, warp)
        #pragma unroll
        for (int mt = 0; mt < 4; mt++) {
            int gmt = wm2*4 + mt;
            int r0 = gmt*16 + r0b, r1 = r0 + 8;
            float s0 = accp[mt][0] + accp[mt][1];
            float q0 = accp[mt][0]*accp[mt][0] + accp[mt][1]*accp[mt][1];
            float s1 = accp[mt][2] + accp[mt][3];
            float q1 = accp[mt][2]*accp[mt][2] + accp[mt][3]*accp[mt][3];
            #pragma unroll
            for (int o = 1; o < 4; o <<= 1) {
                s0 += __shfl_xor_sync(~0u, s0, o); q0 += __shfl_xor_sync(~0u, q0, o);
                s1 += __shfl_xor_sync(~0u, s1, o); q1 += __shfl_xor_sync(~0u, q1, o);
            }
            if ((lane & 3) == 0) {
                red[r0][wn] = make_float2(s0, q0);
                red[r1][wn] = make_float2(s1, q1);
            }
        }
        __syncthreads();

        float g0 = gdp[col], g1 = gdp[col+1];
        float bb0 = bdp[col], bb1 = bdp[col+1];
        #pragma unroll
        for (int mt = 0; mt < 4; mt++) {
            int gmt = wm2*4 + mt;
            int r0 = gmt*16 + r0b, r1 = r0 + 8;
            float mu0, rs0, mu1, rs1;
            ln_stats8(red[r0], 1.f/DP, mu0, rs0);
            ln_stats8(red[r1], 1.f/DP, mu1, rs1);
            size_t base0 = (size_t)(p0 + r0)*DP + col;
            size_t base1 = (size_t)(p0 + r1)*DP + col;
            float2 f0 = *(const float2*)&features[base0];
            float2 f1 = *(const float2*)&features[base1];
            *(float2*)&out[base0] = make_float2(
                (accp[mt][0]-mu0)*rs0*g0 + bb0 + f0.x,
                (accp[mt][1]-mu0)*rs0*g1 + bb1 + f0.y);
            *(float2*)&out[base1] = make_float2(
                (accp[mt][2]-mu1)*rs1*g0 + bb0 + f1.x,
                (accp[mt][3]-mu1)*rs1*g1 + bb1 + f1.y);
        }
    }
}

// ---------------- launch (knn overlapped on a side stream) ----------------
extern "C" void kernel_launch(void* const* d_in, const int* in_sizes, int n_in,
                              void* d_out, int out_size)
{
    const float* xyz      = (const float*)d_in[0];
    const float* features = (const float*)d_in[1];
    const float* W_pre    = (const float*)d_in[2];
    const float* b_pre    = (const float*)d_in[3];
    const float* W_post   = (const float*)d_in[4];
    const float* b_post   = (const float*)d_in[5];
    const float* Wp1      = (const float*)d_in[6];
    const float* Wp2      = (const float*)d_in[7];
    const float* Wa1      = (const float*)d_in[8];
    const float* Wa2      = (const float*)d_in[9];
    const float* WQ       = (const float*)d_in[10];
    const float* WK       = (const float*)d_in[11];
    const float* WV       = (const float*)d_in[12];
    const float* Wproj    = (const float*)d_in[13];
    const float* g_dm     = (const float*)d_in[14];
    const float* b_dm     = (const float*)d_in[15];
    const float* g_dp     = (const float*)d_in[16];
    const float* b_dp     = (const float*)d_in[17];
    float* out = (float*)d_out;

    static cudaStream_t s_knn = nullptr;
    static cudaEvent_t ev_fork = nullptr, ev_knn = nullptr;
    if (!s_knn) {
        cudaStreamCreateWithFlags(&s_knn, cudaStreamNonBlocking);
        cudaEventCreateWithFlags(&ev_fork, cudaEventDisableTiming);
        cudaEventCreateWithFlags(&ev_knn,  cudaEventDisableTiming);
        cudaFuncSetAttribute(knn_kernel, cudaFuncAttributeMaxDynamicSharedMemorySize,
                             NN * (int)sizeof(float4));
        cudaFuncSetAttribute(mega_kernel,     cudaFuncAttributeMaxDynamicSharedMemorySize, MEGA_SMEM);
        cudaFuncSetAttribute(qkvmma_kernel,   cudaFuncAttributeMaxDynamicSharedMemorySize, QKV_SMEM);
        cudaFuncSetAttribute(finalmma_kernel, cudaFuncAttributeMaxDynamicSharedMemorySize, QKV_SMEM);
    }

    cudaEventRecord(ev_fork, 0);
    cudaStreamWaitEvent(s_knn, ev_fork, 0);
    knn_kernel<<<BB*64, 256, NN*sizeof(float4), s_knn>>>(xyz);
    cudaEventRecord(ev_knn, s_knn);

    prep_kernel<<<256, 256>>>(W_pre, WQ, WK, WV, Wproj, W_post, Wp2, Wa1, Wa2);
    qkvmma_kernel<<<NPTS/128, 512, QKV_SMEM>>>(features, b_pre, g_dm, b_dm);

    cudaStreamWaitEvent(0, ev_knn, 0);
    mega_kernel<<<MTOT/128, 512, MEGA_SMEM>>>(xyz, Wp1);

    finalmma_kernel<<<NPTS/128, 512, QKV_SMEM>>>(features, b_post, g_dm, b_dm,
                                                 g_dp, b_dp, out);
}